// round 1
// baseline (speedup 1.0000x reference)
#include <cuda_runtime.h>
#include <math.h>

#define B 2
#define C 64
#define C4 16
#define H 128
#define Wd 128
#define HW (H * Wd)
#define EPSF 1e-6f

// ---------------- scratch (device globals; no allocation allowed) ----------------
__device__ float g_gx[B * C * HW];
__device__ float g_gy[B * C * HW];
__device__ float g_m[B * C * HW];
__device__ float g_md[B * C * HW];
__device__ float g_mdd[B * C * HW];
__device__ float g_ga2[B * C4 * HW];
__device__ float g_cons[B * HW];
__device__ float g_ew[B * HW];
__device__ float g_ee1[B * C * HW];

// ---------------- packed f32x2 helpers (sm_103a FFMA2 path) ----------------
__device__ __forceinline__ unsigned long long pk2(float lo, float hi) {
    unsigned long long r;
    asm("mov.b64 %0, {%1, %2};" : "=l"(r) : "f"(lo), "f"(hi));
    return r;
}
__device__ __forceinline__ void upk2(unsigned long long v, float& lo, float& hi) {
    asm("mov.b64 {%0, %1}, %2;" : "=f"(lo), "=f"(hi) : "l"(v));
}
__device__ __forceinline__ unsigned long long ffma2(unsigned long long a,
                                                    unsigned long long b,
                                                    unsigned long long c) {
    unsigned long long d;
    asm("fma.rn.f32x2 %0, %1, %2, %3;" : "=l"(d) : "l"(a), "l"(b), "l"(c));
    return d;
}

// ---------------- K1: depthwise sobel + mag/dir products ----------------
__global__ __launch_bounds__(256) void k1_sobel(const float* __restrict__ x) {
    __shared__ float sx[18][18];
    int plane = blockIdx.z;                 // b*C + c
    const float* xp = x + (size_t)plane * HW;
    int oy = blockIdx.y * 16, ox = blockIdx.x * 16;
    int tx = threadIdx.x, ty = threadIdx.y;
    int tid = ty * 16 + tx;

    for (int i = tid; i < 18 * 18; i += 256) {
        int r = i / 18, c = i % 18;
        int gh = oy + r - 1, gw = ox + c - 1;
        float v = 0.f;
        if ((unsigned)gh < (unsigned)H && (unsigned)gw < (unsigned)Wd)
            v = xp[gh * Wd + gw];
        sx[r][c] = v;
    }
    __syncthreads();

    float a00 = sx[ty][tx],     a01 = sx[ty][tx + 1],     a02 = sx[ty][tx + 2];
    float a10 = sx[ty + 1][tx],                            a12 = sx[ty + 1][tx + 2];
    float a20 = sx[ty + 2][tx], a21 = sx[ty + 2][tx + 1], a22 = sx[ty + 2][tx + 2];

    float gx = (a02 - a00) + 2.f * (a12 - a10) + (a22 - a20);
    float gy = (a20 - a00) + 2.f * (a21 - a01) + (a22 - a02);

    int idx = plane * HW + (oy + ty) * Wd + (ox + tx);
    g_gx[idx] = gx;
    g_gy[idx] = gy;
    float mag = sqrtf(gx * gx + gy * gy + EPSF);
    float dir = atan2f(gy, gx);
    g_m[idx] = mag;
    g_md[idx] = mag * dir;
    g_mdd[idx] = mag * dir * dir;
}

// ---------------- K2: fused 1x1 chain (128 -> 64 relu -> 16 relu) ----------------
// warp per pixel, 8 pixels per block
__global__ __launch_bounds__(256) void k2_ga(const float* __restrict__ w1,
                                             const float* __restrict__ b1,
                                             const float* __restrict__ w2,
                                             const float* __restrict__ b2) {
    __shared__ __align__(16) float w1t[128 * 64];  // [k][o]
    __shared__ __align__(16) float w2t[64 * 16];   // [k][o]
    __shared__ float b1s[64], b2s[16];
    __shared__ __align__(16) float sv[8][128];
    __shared__ __align__(16) float hs[8][64];

    int tid = threadIdx.x;
    for (int i = tid; i < 128 * 64; i += 256) {
        int o = i / 128, k = i % 128;
        w1t[k * 64 + o] = w1[i];
    }
    for (int i = tid; i < 64 * 16; i += 256) {
        int o = i / 64, k = i % 64;
        w2t[k * 16 + o] = w2[i];
    }
    if (tid < 64) b1s[tid] = b1[tid];
    if (tid < 16) b2s[tid] = b2[tid];

    int b = blockIdx.x / (HW / 8);
    int hw0 = (blockIdx.x % (HW / 8)) * 8;
    const float* gxp = g_gx + (size_t)b * C * HW + hw0;
    const float* gyp = g_gy + (size_t)b * C * HW + hw0;
    for (int i = tid; i < 1024; i += 256) {
        int k = i >> 3, px = i & 7;
        float v = (k < 64) ? gxp[k * HW + px] : gyp[(k - 64) * HW + px];
        sv[px][k] = v;
    }
    __syncthreads();

    int w = tid >> 5, l = tid & 31;
    float acc0 = b1s[2 * l], acc1 = b1s[2 * l + 1];
    const float* svp = sv[w];
#pragma unroll
    for (int k = 0; k < 128; k += 4) {
        float4 v = *reinterpret_cast<const float4*>(svp + k);
        float2 wa = *reinterpret_cast<const float2*>(w1t + (k + 0) * 64 + 2 * l);
        acc0 += wa.x * v.x; acc1 += wa.y * v.x;
        float2 wb = *reinterpret_cast<const float2*>(w1t + (k + 1) * 64 + 2 * l);
        acc0 += wb.x * v.y; acc1 += wb.y * v.y;
        float2 wc = *reinterpret_cast<const float2*>(w1t + (k + 2) * 64 + 2 * l);
        acc0 += wc.x * v.z; acc1 += wc.y * v.z;
        float2 wdp = *reinterpret_cast<const float2*>(w1t + (k + 3) * 64 + 2 * l);
        acc0 += wdp.x * v.w; acc1 += wdp.y * v.w;
    }
    reinterpret_cast<float2*>(hs[w])[l] =
        make_float2(fmaxf(acc0, 0.f), fmaxf(acc1, 0.f));
    __syncwarp();

    if (l < 16) {
        float acc = b2s[l];
#pragma unroll
        for (int k = 0; k < 64; k++) acc += w2t[k * 16 + l] * hs[w][k];
        g_ga2[((size_t)b * C4 + l) * HW + hw0 + w] = fmaxf(acc, 0.f);
    }
}

// ---------------- K3: windowed weighted direction stats + channel mean ----------------
__global__ __launch_bounds__(256) void k3_cons() {
    __shared__ float sm0[20][20];
    __shared__ float sm1[20][20];
    __shared__ float sm2[20][20];
    int b = blockIdx.z;
    int oy = blockIdx.y * 16, ox = blockIdx.x * 16;
    int tx = threadIdx.x, ty = threadIdx.y;
    int tid = ty * 16 + tx;

    float cons = 0.f;
    for (int c = 0; c < C; c++) {
        __syncthreads();
        int base = (b * C + c) * HW;
        for (int i = tid; i < 400; i += 256) {
            int r = i / 20, cc = i % 20;
            int gh = oy + r - 2, gw = ox + cc - 2;
            bool ok = (unsigned)gh < (unsigned)H && (unsigned)gw < (unsigned)Wd;
            int gi = base + gh * Wd + gw;
            sm0[r][cc] = ok ? g_m[gi] : 0.f;
            sm1[r][cc] = ok ? g_md[gi] : 0.f;
            sm2[r][cc] = ok ? g_mdd[gi] : 0.f;
        }
        __syncthreads();
        float s0 = 0.f, s1 = 0.f, s2 = 0.f;
#pragma unroll
        for (int dy = 0; dy < 5; dy++)
#pragma unroll
            for (int dx = 0; dx < 5; dx++) {
                s0 += sm0[ty + dy][tx + dx];
                s1 += sm1[ty + dy][tx + dx];
                s2 += sm2[ty + dy][tx + dx];
            }
        float inv = 1.f / (s0 + EPSF);
        float wmean = s1 * inv;
        float wvar = (s2 - 2.f * wmean * s1 + wmean * wmean * s0) * inv;
        wvar = fmaxf(wvar, 0.f);
        cons += 1.f - tanhf(sqrtf(wvar));
    }
    g_cons[b * HW + (oy + ty) * Wd + (ox + tx)] = cons * (1.f / (float)C);
}

// ---------------- K4: cd branch (3x3 16->16 relu, 1x1 16->1, sigmoid, * cons) ----------------
__global__ __launch_bounds__(256) void k4_cd(const float* __restrict__ cw1,
                                             const float* __restrict__ cb1,
                                             const float* __restrict__ cw2,
                                             const float* __restrict__ cb2) {
    __shared__ float sga[C4][18][18];
    __shared__ float w1s[C4 * C4 * 9];
    __shared__ float w2s[C4], b1s[C4];
    __shared__ float b2s_;
    int b = blockIdx.z;
    int oy = blockIdx.y * 16, ox = blockIdx.x * 16;
    int tx = threadIdx.x, ty = threadIdx.y;
    int tid = ty * 16 + tx;

    for (int i = tid; i < C4 * C4 * 9; i += 256) w1s[i] = cw1[i];
    if (tid < C4) { w2s[tid] = cw2[tid]; b1s[tid] = cb1[tid]; }
    if (tid == 0) b2s_ = cb2[0];

    for (int i = tid; i < C4 * 324; i += 256) {
        int ic = i / 324, j = i % 324;
        int r = j / 18, cc = j % 18;
        int gh = oy + r - 1, gw = ox + cc - 1;
        float v = 0.f;
        if ((unsigned)gh < (unsigned)H && (unsigned)gw < (unsigned)Wd)
            v = g_ga2[((size_t)b * C4 + ic) * HW + gh * Wd + gw];
        sga[ic][r][cc] = v;
    }
    __syncthreads();

    float acc[C4];
#pragma unroll
    for (int o = 0; o < C4; o++) acc[o] = b1s[o];

    for (int ic = 0; ic < C4; ic++) {
        float win[9];
#pragma unroll
        for (int dy = 0; dy < 3; dy++)
#pragma unroll
            for (int dx = 0; dx < 3; dx++)
                win[dy * 3 + dx] = sga[ic][ty + dy][tx + dx];
#pragma unroll
        for (int o = 0; o < C4; o++) {
            const float* wp = &w1s[(o * C4 + ic) * 9];
#pragma unroll
            for (int k = 0; k < 9; k++) acc[o] += wp[k] * win[k];
        }
    }
    float s = b2s_;
#pragma unroll
    for (int o = 0; o < C4; o++) s += w2s[o] * fmaxf(acc[o], 0.f);
    float sig = 1.f / (1.f + expf(-s));
    int hw = (oy + ty) * Wd + (ox + tx);
    g_ew[b * HW + hw] = sig * g_cons[b * HW + hw];
}

// ---------------- K5/K6: 3x3 conv 64->64, FFMA2 micro-kernel ----------------
// 32x32 spatial tile, 8 output channels per block, 2x2 px per thread
__global__ __launch_bounds__(256) void k56_conv(const float* __restrict__ wt,
                                                const float* __restrict__ bias,
                                                int mode,  // 0: relu->g_ee1, 1: residual->out
                                                const float* __restrict__ xres,
                                                const float* __restrict__ alphap,
                                                float* __restrict__ out) {
    __shared__ float sh[34][34];
    __shared__ __align__(16) float2 ws[8][9];

    int b = blockIdx.z >> 3;
    int ocg = blockIdx.z & 7;
    int oy = blockIdx.y * 32, ox = blockIdx.x * 32;
    int tx = threadIdx.x, ty = threadIdx.y;
    int tid = ty * 16 + tx;

    unsigned long long acc[8][2];
#pragma unroll
    for (int o = 0; o < 8; o++) {
        float bv = bias[ocg * 8 + o];
        unsigned long long bp = pk2(bv, bv);
        acc[o][0] = bp;
        acc[o][1] = bp;
    }

    const float* inb = (mode == 0) ? (xres + (size_t)b * C * HW)
                                   : (g_ee1 + (size_t)b * C * HW);

    for (int ic = 0; ic < C; ic++) {
        __syncthreads();
        const float* ip = inb + (size_t)ic * HW;
        for (int i = tid; i < 34 * 34; i += 256) {
            int r = i / 34, c = i % 34;
            int gh = oy + r - 1, gw = ox + c - 1;
            float v = 0.f;
            if ((unsigned)gh < (unsigned)H && (unsigned)gw < (unsigned)Wd)
                v = ip[gh * Wd + gw];
            sh[r][c] = v;
        }
        if (tid < 72) {
            int o = tid / 9, k = tid % 9;
            float wv = wt[((size_t)(ocg * 8 + o) * C + ic) * 9 + k];
            ws[o][k] = make_float2(wv, wv);
        }
        __syncthreads();

        // 4x4 input patch for this thread's 2x2 outputs
        float iv[4][4];
#pragma unroll
        for (int r = 0; r < 4; r++) {
            float2 p0 = *reinterpret_cast<const float2*>(&sh[2 * ty + r][2 * tx]);
            float2 p1 = *reinterpret_cast<const float2*>(&sh[2 * ty + r][2 * tx + 2]);
            iv[r][0] = p0.x; iv[r][1] = p0.y; iv[r][2] = p1.x; iv[r][3] = p1.y;
        }
        unsigned long long pr[4][3];
#pragma unroll
        for (int r = 0; r < 4; r++)
#pragma unroll
            for (int kx = 0; kx < 3; kx++)
                pr[r][kx] = pk2(iv[r][kx], iv[r][kx + 1]);

#pragma unroll
        for (int o = 0; o < 8; o++) {
#pragma unroll
            for (int ky = 0; ky < 3; ky++) {
#pragma unroll
                for (int kx = 0; kx < 3; kx++) {
                    unsigned long long wv =
                        *reinterpret_cast<const unsigned long long*>(&ws[o][ky * 3 + kx]);
                    acc[o][0] = ffma2(wv, pr[ky][kx], acc[o][0]);
                    acc[o][1] = ffma2(wv, pr[ky + 1][kx], acc[o][1]);
                }
            }
        }
    }

    float alpha = *alphap;
#pragma unroll
    for (int o = 0; o < 8; o++) {
        int oc = ocg * 8 + o;
#pragma unroll
        for (int r = 0; r < 2; r++) {
            float v0, v1;
            upk2(acc[o][r], v0, v1);
            int h = oy + 2 * ty + r;
            int w0 = ox + 2 * tx;
            size_t oidx = ((size_t)b * C + oc) * HW + h * Wd + w0;
            if (mode == 0) {
                g_ee1[oidx] = fmaxf(v0, 0.f);
                g_ee1[oidx + 1] = fmaxf(v1, 0.f);
            } else {
                float e0 = g_ew[b * HW + h * Wd + w0];
                float e1 = g_ew[b * HW + h * Wd + w0 + 1];
                out[oidx] = xres[oidx] + alpha * e0 * v0;
                out[oidx + 1] = xres[oidx + 1] + alpha * e1 * v1;
            }
        }
    }
}

// ---------------- launch ----------------
extern "C" void kernel_launch(void* const* d_in, const int* in_sizes, int n_in,
                              void* d_out, int out_size) {
    const float* x     = (const float*)d_in[0];
    const float* ga_w1 = (const float*)d_in[3];
    const float* ga_b1 = (const float*)d_in[4];
    const float* ga_w2 = (const float*)d_in[5];
    const float* ga_b2 = (const float*)d_in[6];
    const float* cd_w1 = (const float*)d_in[7];
    const float* cd_b1 = (const float*)d_in[8];
    const float* cd_w2 = (const float*)d_in[9];
    const float* cd_b2 = (const float*)d_in[10];
    const float* ec_w1 = (const float*)d_in[11];
    const float* ec_b1 = (const float*)d_in[12];
    const float* ec_w2 = (const float*)d_in[13];
    const float* ec_b2 = (const float*)d_in[14];
    const float* alpha = (const float*)d_in[15];
    float* out = (float*)d_out;

    k1_sobel<<<dim3(8, 8, B * C), dim3(16, 16)>>>(x);
    k2_ga<<<B * HW / 8, 256>>>(ga_w1, ga_b1, ga_w2, ga_b2);
    k3_cons<<<dim3(8, 8, B), dim3(16, 16)>>>();
    k4_cd<<<dim3(8, 8, B), dim3(16, 16)>>>(cd_w1, cd_b1, cd_w2, cd_b2);
    k56_conv<<<dim3(4, 4, B * 8), dim3(16, 16)>>>(ec_w1, ec_b1, 0, x, alpha, out);
    k56_conv<<<dim3(4, 4, B * 8), dim3(16, 16)>>>(ec_w2, ec_b2, 1, x, alpha, out);
}

// round 2
// speedup vs baseline: 1.4095x; 1.4095x over previous
#include <cuda_runtime.h>
#include <math.h>

#define B 2
#define C 64
#define C4 16
#define H 128
#define Wd 128
#define HW (H * Wd)
#define EPSF 1e-6f

// ---------------- scratch (device globals; no allocation allowed) ----------------
__device__ float g_gx[B * C * HW];
__device__ float g_gy[B * C * HW];
__device__ float g_ga2[B * C4 * HW];
__device__ float g_cons[B * HW];
__device__ float g_ew[B * HW];
__device__ float g_ee1[B * C * HW];

// ---------------- packed f32x2 helpers (sm_103a FFMA2 path) ----------------
__device__ __forceinline__ unsigned long long pk2(float lo, float hi) {
    unsigned long long r;
    asm("mov.b64 %0, {%1, %2};" : "=l"(r) : "f"(lo), "f"(hi));
    return r;
}
__device__ __forceinline__ void upk2(unsigned long long v, float& lo, float& hi) {
    asm("mov.b64 {%0, %1}, %2;" : "=f"(lo), "=f"(hi) : "l"(v));
}
__device__ __forceinline__ unsigned long long ffma2(unsigned long long a,
                                                    unsigned long long b,
                                                    unsigned long long c) {
    unsigned long long d;
    asm("fma.rn.f32x2 %0, %1, %2, %3;" : "=l"(d) : "l"(a), "l"(b), "l"(c));
    return d;
}

// ---------------- K0: zero the consistency accumulator ----------------
__global__ __launch_bounds__(256) void k0_zero() {
    int i = blockIdx.x * 256 + threadIdx.x;
    if (i < B * HW) g_cons[i] = 0.f;
}

// ---------------- K1: depthwise sobel ----------------
__global__ __launch_bounds__(256) void k1_sobel(const float* __restrict__ x) {
    __shared__ float sx[18][18];
    int plane = blockIdx.z;                 // b*C + c
    const float* xp = x + (size_t)plane * HW;
    int oy = blockIdx.y * 16, ox = blockIdx.x * 16;
    int tx = threadIdx.x, ty = threadIdx.y;
    int tid = ty * 16 + tx;

    for (int i = tid; i < 18 * 18; i += 256) {
        int r = i / 18, c = i % 18;
        int gh = oy + r - 1, gw = ox + c - 1;
        float v = 0.f;
        if ((unsigned)gh < (unsigned)H && (unsigned)gw < (unsigned)Wd)
            v = xp[gh * Wd + gw];
        sx[r][c] = v;
    }
    __syncthreads();

    float a00 = sx[ty][tx],     a01 = sx[ty][tx + 1],     a02 = sx[ty][tx + 2];
    float a10 = sx[ty + 1][tx],                            a12 = sx[ty + 1][tx + 2];
    float a20 = sx[ty + 2][tx], a21 = sx[ty + 2][tx + 1], a22 = sx[ty + 2][tx + 2];

    float gx = (a02 - a00) + 2.f * (a12 - a10) + (a22 - a20);
    float gy = (a20 - a00) + 2.f * (a21 - a01) + (a22 - a02);

    int idx = plane * HW + (oy + ty) * Wd + (ox + tx);
    g_gx[idx] = gx;
    g_gy[idx] = gy;
}

// ---------------- K2: fused 1x1 chain (128 -> 64 relu -> 16 relu) ----------------
// 64 pixels per block (8 iterations of warp-per-pixel x 8 warps)
__global__ __launch_bounds__(256) void k2_ga(const float* __restrict__ w1,
                                             const float* __restrict__ b1,
                                             const float* __restrict__ w2,
                                             const float* __restrict__ b2) {
    __shared__ __align__(16) float w1t[128 * 64];  // [k][o]
    __shared__ __align__(16) float w2t[64 * 16];   // [k][o]
    __shared__ float b1s[64], b2s[16];
    __shared__ __align__(16) float sv[8][128];
    __shared__ __align__(16) float hs[8][64];

    int tid = threadIdx.x;
    for (int i = tid; i < 128 * 64; i += 256) {
        int o = i / 128, k = i % 128;
        w1t[k * 64 + o] = w1[i];
    }
    for (int i = tid; i < 64 * 16; i += 256) {
        int o = i / 64, k = i % 64;
        w2t[k * 16 + o] = w2[i];
    }
    if (tid < 64) b1s[tid] = b1[tid];
    if (tid < 16) b2s[tid] = b2[tid];

    int b = blockIdx.x / (HW / 64);
    int hw00 = (blockIdx.x % (HW / 64)) * 64;
    int w = tid >> 5, l = tid & 31;

    for (int it = 0; it < 8; it++) {
        int hw0 = hw00 + it * 8;
        const float* gxp = g_gx + (size_t)b * C * HW + hw0;
        const float* gyp = g_gy + (size_t)b * C * HW + hw0;
        __syncthreads();
        for (int i = tid; i < 1024; i += 256) {
            int k = i >> 3, px = i & 7;
            float v = (k < 64) ? gxp[k * HW + px] : gyp[(k - 64) * HW + px];
            sv[px][k] = v;
        }
        __syncthreads();

        float acc0 = b1s[2 * l], acc1 = b1s[2 * l + 1];
        const float* svp = sv[w];
#pragma unroll
        for (int k = 0; k < 128; k += 4) {
            float4 v = *reinterpret_cast<const float4*>(svp + k);
            float2 wa = *reinterpret_cast<const float2*>(w1t + (k + 0) * 64 + 2 * l);
            acc0 += wa.x * v.x; acc1 += wa.y * v.x;
            float2 wb = *reinterpret_cast<const float2*>(w1t + (k + 1) * 64 + 2 * l);
            acc0 += wb.x * v.y; acc1 += wb.y * v.y;
            float2 wc = *reinterpret_cast<const float2*>(w1t + (k + 2) * 64 + 2 * l);
            acc0 += wc.x * v.z; acc1 += wc.y * v.z;
            float2 wdp = *reinterpret_cast<const float2*>(w1t + (k + 3) * 64 + 2 * l);
            acc0 += wdp.x * v.w; acc1 += wdp.y * v.w;
        }
        reinterpret_cast<float2*>(hs[w])[l] =
            make_float2(fmaxf(acc0, 0.f), fmaxf(acc1, 0.f));
        __syncwarp();

        if (l < 16) {
            float acc = b2s[l];
#pragma unroll
            for (int k = 0; k < 64; k++) acc += w2t[k * 16 + l] * hs[w][k];
            g_ga2[((size_t)b * C4 + l) * HW + hw0 + w] = fmaxf(acc, 0.f);
        }
    }
}

// ---------------- K3: windowed weighted direction stats (separable box sums) ----------------
// grid z = B*16 channel groups of 4; partial channel means via atomicAdd
__global__ __launch_bounds__(256) void k3_cons() {
    __shared__ float sm0[20][20];
    __shared__ float sm1[20][20];
    __shared__ float sm2[20][20];
    __shared__ float h0[20][16];
    __shared__ float h1[20][16];
    __shared__ float h2[20][16];
    int b = blockIdx.z >> 4;
    int cg = blockIdx.z & 15;
    int oy = blockIdx.y * 16, ox = blockIdx.x * 16;
    int tx = threadIdx.x, ty = threadIdx.y;
    int tid = ty * 16 + tx;

    float cons = 0.f;
    for (int cc = 0; cc < 4; cc++) {
        int c = cg * 4 + cc;
        int base = (b * C + c) * HW;
        __syncthreads();
        for (int i = tid; i < 400; i += 256) {
            int r = i / 20, k = i % 20;
            int gh = oy + r - 2, gw = ox + k - 2;
            float m0 = 0.f, m1 = 0.f, m2 = 0.f;
            if ((unsigned)gh < (unsigned)H && (unsigned)gw < (unsigned)Wd) {
                int gi = base + gh * Wd + gw;
                float gx = g_gx[gi], gy = g_gy[gi];
                float mag = sqrtf(gx * gx + gy * gy + EPSF);
                float dir = atan2f(gy, gx);
                m0 = mag;
                m1 = mag * dir;
                m2 = m1 * dir;
            }
            sm0[r][k] = m0;
            sm1[r][k] = m1;
            sm2[r][k] = m2;
        }
        __syncthreads();
        // horizontal 5-tap sums
        for (int i = tid; i < 320; i += 256) {
            int r = i / 16, k = i % 16;
            float a0 = 0.f, a1 = 0.f, a2 = 0.f;
#pragma unroll
            for (int d = 0; d < 5; d++) {
                a0 += sm0[r][k + d];
                a1 += sm1[r][k + d];
                a2 += sm2[r][k + d];
            }
            h0[r][k] = a0;
            h1[r][k] = a1;
            h2[r][k] = a2;
        }
        __syncthreads();
        // vertical 5-tap sums + stats
        float s0 = 0.f, s1 = 0.f, s2 = 0.f;
#pragma unroll
        for (int d = 0; d < 5; d++) {
            s0 += h0[ty + d][tx];
            s1 += h1[ty + d][tx];
            s2 += h2[ty + d][tx];
        }
        float inv = 1.f / (s0 + EPSF);
        float wmean = s1 * inv;
        float wvar = (s2 - 2.f * wmean * s1 + wmean * wmean * s0) * inv;
        wvar = fmaxf(wvar, 0.f);
        cons += 1.f - tanhf(sqrtf(wvar));
    }
    atomicAdd(&g_cons[b * HW + (oy + ty) * Wd + (ox + tx)], cons * (1.f / (float)C));
}

// ---------------- K4: cd branch (3x3 16->16 relu, 1x1 16->1, sigmoid, * cons) ----------------
__global__ __launch_bounds__(256) void k4_cd(const float* __restrict__ cw1,
                                             const float* __restrict__ cb1,
                                             const float* __restrict__ cw2,
                                             const float* __restrict__ cb2) {
    __shared__ float sga[C4][18][18];
    __shared__ float w1s[C4 * C4 * 9];
    __shared__ float w2s[C4], b1s[C4];
    __shared__ float b2s_;
    int b = blockIdx.z;
    int oy = blockIdx.y * 16, ox = blockIdx.x * 16;
    int tx = threadIdx.x, ty = threadIdx.y;
    int tid = ty * 16 + tx;

    for (int i = tid; i < C4 * C4 * 9; i += 256) w1s[i] = cw1[i];
    if (tid < C4) { w2s[tid] = cw2[tid]; b1s[tid] = cb1[tid]; }
    if (tid == 0) b2s_ = cb2[0];

    for (int i = tid; i < C4 * 324; i += 256) {
        int ic = i / 324, j = i % 324;
        int r = j / 18, cc = j % 18;
        int gh = oy + r - 1, gw = ox + cc - 1;
        float v = 0.f;
        if ((unsigned)gh < (unsigned)H && (unsigned)gw < (unsigned)Wd)
            v = g_ga2[((size_t)b * C4 + ic) * HW + gh * Wd + gw];
        sga[ic][r][cc] = v;
    }
    __syncthreads();

    float acc[C4];
#pragma unroll
    for (int o = 0; o < C4; o++) acc[o] = b1s[o];

    for (int ic = 0; ic < C4; ic++) {
        float win[9];
#pragma unroll
        for (int dy = 0; dy < 3; dy++)
#pragma unroll
            for (int dx = 0; dx < 3; dx++)
                win[dy * 3 + dx] = sga[ic][ty + dy][tx + dx];
#pragma unroll
        for (int o = 0; o < C4; o++) {
            const float* wp = &w1s[(o * C4 + ic) * 9];
#pragma unroll
            for (int k = 0; k < 9; k++) acc[o] += wp[k] * win[k];
        }
    }
    float s = b2s_;
#pragma unroll
    for (int o = 0; o < C4; o++) s += w2s[o] * fmaxf(acc[o], 0.f);
    float sig = 1.f / (1.f + expf(-s));
    int hw = (oy + ty) * Wd + (ox + tx);
    g_ew[b * HW + hw] = sig * g_cons[b * HW + hw];
}

// ---------------- K5/K6: 3x3 conv 64->64, FFMA2 micro-kernel ----------------
// 32x32 spatial tile, 8 output channels per block, 2x2 px per thread
__global__ __launch_bounds__(256) void k56_conv(const float* __restrict__ wt,
                                                const float* __restrict__ bias,
                                                int mode,  // 0: relu->g_ee1, 1: residual->out
                                                const float* __restrict__ xres,
                                                const float* __restrict__ alphap,
                                                float* __restrict__ out) {
    __shared__ float sh[34][34];
    __shared__ __align__(16) float2 ws[8][9];

    int b = blockIdx.z >> 3;
    int ocg = blockIdx.z & 7;
    int oy = blockIdx.y * 32, ox = blockIdx.x * 32;
    int tx = threadIdx.x, ty = threadIdx.y;
    int tid = ty * 16 + tx;

    unsigned long long acc[8][2];
#pragma unroll
    for (int o = 0; o < 8; o++) {
        float bv = bias[ocg * 8 + o];
        unsigned long long bp = pk2(bv, bv);
        acc[o][0] = bp;
        acc[o][1] = bp;
    }

    const float* inb = (mode == 0) ? (xres + (size_t)b * C * HW)
                                   : (g_ee1 + (size_t)b * C * HW);

    for (int ic = 0; ic < C; ic++) {
        __syncthreads();
        const float* ip = inb + (size_t)ic * HW;
        for (int i = tid; i < 34 * 34; i += 256) {
            int r = i / 34, c = i % 34;
            int gh = oy + r - 1, gw = ox + c - 1;
            float v = 0.f;
            if ((unsigned)gh < (unsigned)H && (unsigned)gw < (unsigned)Wd)
                v = ip[gh * Wd + gw];
            sh[r][c] = v;
        }
        if (tid < 72) {
            int o = tid / 9, k = tid % 9;
            float wv = wt[((size_t)(ocg * 8 + o) * C + ic) * 9 + k];
            ws[o][k] = make_float2(wv, wv);
        }
        __syncthreads();

        // 4x4 input patch for this thread's 2x2 outputs
        float iv[4][4];
#pragma unroll
        for (int r = 0; r < 4; r++) {
            float2 p0 = *reinterpret_cast<const float2*>(&sh[2 * ty + r][2 * tx]);
            float2 p1 = *reinterpret_cast<const float2*>(&sh[2 * ty + r][2 * tx + 2]);
            iv[r][0] = p0.x; iv[r][1] = p0.y; iv[r][2] = p1.x; iv[r][3] = p1.y;
        }
        unsigned long long pr[4][3];
#pragma unroll
        for (int r = 0; r < 4; r++)
#pragma unroll
            for (int kx = 0; kx < 3; kx++)
                pr[r][kx] = pk2(iv[r][kx], iv[r][kx + 1]);

#pragma unroll
        for (int o = 0; o < 8; o++) {
#pragma unroll
            for (int ky = 0; ky < 3; ky++) {
#pragma unroll
                for (int kx = 0; kx < 3; kx++) {
                    unsigned long long wv =
                        *reinterpret_cast<const unsigned long long*>(&ws[o][ky * 3 + kx]);
                    acc[o][0] = ffma2(wv, pr[ky][kx], acc[o][0]);
                    acc[o][1] = ffma2(wv, pr[ky + 1][kx], acc[o][1]);
                }
            }
        }
    }

    float alpha = *alphap;
#pragma unroll
    for (int o = 0; o < 8; o++) {
        int oc = ocg * 8 + o;
#pragma unroll
        for (int r = 0; r < 2; r++) {
            float v0, v1;
            upk2(acc[o][r], v0, v1);
            int h = oy + 2 * ty + r;
            int w0 = ox + 2 * tx;
            size_t oidx = ((size_t)b * C + oc) * HW + h * Wd + w0;
            if (mode == 0) {
                g_ee1[oidx] = fmaxf(v0, 0.f);
                g_ee1[oidx + 1] = fmaxf(v1, 0.f);
            } else {
                float e0 = g_ew[b * HW + h * Wd + w0];
                float e1 = g_ew[b * HW + h * Wd + w0 + 1];
                out[oidx] = xres[oidx] + alpha * e0 * v0;
                out[oidx + 1] = xres[oidx + 1] + alpha * e1 * v1;
            }
        }
    }
}

// ---------------- launch ----------------
extern "C" void kernel_launch(void* const* d_in, const int* in_sizes, int n_in,
                              void* d_out, int out_size) {
    const float* x     = (const float*)d_in[0];
    const float* ga_w1 = (const float*)d_in[3];
    const float* ga_b1 = (const float*)d_in[4];
    const float* ga_w2 = (const float*)d_in[5];
    const float* ga_b2 = (const float*)d_in[6];
    const float* cd_w1 = (const float*)d_in[7];
    const float* cd_b1 = (const float*)d_in[8];
    const float* cd_w2 = (const float*)d_in[9];
    const float* cd_b2 = (const float*)d_in[10];
    const float* ec_w1 = (const float*)d_in[11];
    const float* ec_b1 = (const float*)d_in[12];
    const float* ec_w2 = (const float*)d_in[13];
    const float* ec_b2 = (const float*)d_in[14];
    const float* alpha = (const float*)d_in[15];
    float* out = (float*)d_out;

    k0_zero<<<(B * HW + 255) / 256, 256>>>();
    k1_sobel<<<dim3(8, 8, B * C), dim3(16, 16)>>>(x);
    k2_ga<<<B * HW / 64, 256>>>(ga_w1, ga_b1, ga_w2, ga_b2);
    k3_cons<<<dim3(8, 8, B * 16), dim3(16, 16)>>>();
    k4_cd<<<dim3(8, 8, B), dim3(16, 16)>>>(cd_w1, cd_b1, cd_w2, cd_b2);
    k56_conv<<<dim3(4, 4, B * 8), dim3(16, 16)>>>(ec_w1, ec_b1, 0, x, alpha, out);
    k56_conv<<<dim3(4, 4, B * 8), dim3(16, 16)>>>(ec_w2, ec_b2, 1, x, alpha, out);
}

// round 3
// speedup vs baseline: 2.1565x; 1.5300x over previous
#include <cuda_runtime.h>
#include <math.h>

#define B 2
#define C 64
#define C4 16
#define H 128
#define Wd 128
#define HW (H * Wd)
#define EPSF 1e-6f

// ---------------- scratch (device globals; no allocation allowed) ----------------
__device__ float g_gx[B * C * HW];
__device__ float g_gy[B * C * HW];
__device__ float g_ga2[B * C4 * HW];
__device__ float g_cons[B * HW];
__device__ float g_ew[B * HW];
__device__ float g_ee1[B * C * HW];

typedef unsigned long long u64;

// ---------------- packed f32x2 helpers (sm_103a FFMA2 path) ----------------
__device__ __forceinline__ u64 pk2(float lo, float hi) {
    u64 r;
    asm("mov.b64 %0, {%1, %2};" : "=l"(r) : "f"(lo), "f"(hi));
    return r;
}
__device__ __forceinline__ void upk2(u64 v, float& lo, float& hi) {
    asm("mov.b64 {%0, %1}, %2;" : "=f"(lo), "=f"(hi) : "l"(v));
}
__device__ __forceinline__ u64 ffma2(u64 a, u64 b, u64 c) {
    u64 d;
    asm("fma.rn.f32x2 %0, %1, %2, %3;" : "=l"(d) : "l"(a), "l"(b), "l"(c));
    return d;
}

// ---------------- K0: zero the consistency accumulator ----------------
__global__ __launch_bounds__(256) void k0_zero() {
    int i = blockIdx.x * 256 + threadIdx.x;
    if (i < B * HW) g_cons[i] = 0.f;
}

// ---------------- K1: depthwise sobel ----------------
__global__ __launch_bounds__(256) void k1_sobel(const float* __restrict__ x) {
    __shared__ float sx[18][18];
    int plane = blockIdx.z;                 // b*C + c
    const float* xp = x + (size_t)plane * HW;
    int oy = blockIdx.y * 16, ox = blockIdx.x * 16;
    int tx = threadIdx.x, ty = threadIdx.y;
    int tid = ty * 16 + tx;

    for (int i = tid; i < 18 * 18; i += 256) {
        int r = i / 18, c = i % 18;
        int gh = oy + r - 1, gw = ox + c - 1;
        float v = 0.f;
        if ((unsigned)gh < (unsigned)H && (unsigned)gw < (unsigned)Wd)
            v = xp[gh * Wd + gw];
        sx[r][c] = v;
    }
    __syncthreads();

    float a00 = sx[ty][tx],     a01 = sx[ty][tx + 1],     a02 = sx[ty][tx + 2];
    float a10 = sx[ty + 1][tx],                            a12 = sx[ty + 1][tx + 2];
    float a20 = sx[ty + 2][tx], a21 = sx[ty + 2][tx + 1], a22 = sx[ty + 2][tx + 2];

    float gx = (a02 - a00) + 2.f * (a12 - a10) + (a22 - a20);
    float gy = (a20 - a00) + 2.f * (a21 - a01) + (a22 - a02);

    int idx = plane * HW + (oy + ty) * Wd + (ox + tx);
    g_gx[idx] = gx;
    g_gy[idx] = gy;
}

// ---------------- K2: fused 1x1 chain (128 -> 64 relu -> 16 relu) ----------------
// thread owns 2 adjacent pixels; inputs streamed from gmem (L2) with prefetch;
// layer1 accumulators packed over output-pairs, layer2 fused in registers.
__global__ __launch_bounds__(128) void k2_ga(const float* __restrict__ w1,
                                             const float* __restrict__ b1,
                                             const float* __restrict__ w2,
                                             const float* __restrict__ b2) {
    __shared__ __align__(16) float w1t[128 * 64];   // [k][o]  32KB
    __shared__ __align__(16) u64 w2d[64 * 16];      // (w,w) [h][o2] 8KB
    __shared__ __align__(16) float b1t[64];
    __shared__ __align__(16) u64 b2d[16];

    int tid = threadIdx.x;
    for (int i = tid; i < 128 * 64; i += 128) {
        int o = i >> 7, k = i & 127;
        w1t[k * 64 + o] = w1[i];               // w1[o*128+k]
    }
    for (int i = tid; i < 64 * 16; i += 128) {
        int o2 = i >> 6, h = i & 63;
        float w = w2[i];                       // w2[o2*64+h]
        w2d[h * 16 + o2] = pk2(w, w);
    }
    if (tid < 64) b1t[tid] = b1[tid];
    if (tid < 16) b2d[tid] = pk2(b2[tid], b2[tid]);
    __syncthreads();

    int b = blockIdx.x >> 6;
    int p0 = ((blockIdx.x & 63) * 128 + tid) * 2;
    const float* gxp = g_gx + (size_t)b * C * HW + p0;
    const float* gyp = g_gy + (size_t)b * C * HW + p0;

    u64 acc2[16];
#pragma unroll
    for (int o = 0; o < 16; o++) acc2[o] = b2d[o];

#pragma unroll 1
    for (int p = 0; p < 4; p++) {
        int op = p * 16;
        u64 accA[8], accB[8];   // px0 / px1, packed over (o, o+1)
        const u64* b1p = reinterpret_cast<const u64*>(&b1t[op]);
#pragma unroll
        for (int q = 0; q < 8; q++) { accA[q] = b1p[q]; accB[q] = b1p[q]; }

        u64 v[8];
#pragma unroll
        for (int j = 0; j < 8; j++)
            v[j] = *reinterpret_cast<const u64*>(gxp + j * HW);

#pragma unroll 1
        for (int g = 0; g < 16; g++) {
            u64 nv[8];
            if (g < 15) {
                const float* s = (g < 7) ? (gxp + (g + 1) * 8 * HW)
                                         : (gyp + ((g + 1) * 8 - 64) * HW);
#pragma unroll
                for (int j = 0; j < 8; j++)
                    nv[j] = *reinterpret_cast<const u64*>(s + j * HW);
            }
#pragma unroll
            for (int j = 0; j < 8; j++) {
                int k = g * 8 + j;
                float v0, v1;
                upk2(v[j], v0, v1);
                u64 va = pk2(v0, v0), vb = pk2(v1, v1);
                const ulonglong2* wr =
                    reinterpret_cast<const ulonglong2*>(&w1t[k * 64 + op]);
#pragma unroll
                for (int q = 0; q < 4; q++) {
                    ulonglong2 wp = wr[q];          // (w_{op+4q},w_{+1}) (w_{+2},w_{+3})
                    accA[2 * q]     = ffma2(wp.x, va, accA[2 * q]);
                    accA[2 * q + 1] = ffma2(wp.y, va, accA[2 * q + 1]);
                    accB[2 * q]     = ffma2(wp.x, vb, accB[2 * q]);
                    accB[2 * q + 1] = ffma2(wp.y, vb, accB[2 * q + 1]);
                }
            }
            if (g < 15) {
#pragma unroll
                for (int j = 0; j < 8; j++) v[j] = nv[j];
            }
        }
        // relu + layer2 (transpose o-pair packing -> px packing)
#pragma unroll
        for (int hp = 0; hp < 8; hp++) {
            float a0, a1, c0, c1;
            upk2(accA[hp], a0, a1);
            upk2(accB[hp], c0, c1);
            u64 hv0 = pk2(fmaxf(a0, 0.f), fmaxf(c0, 0.f));   // hidden op+2hp, (px0,px1)
            u64 hv1 = pk2(fmaxf(a1, 0.f), fmaxf(c1, 0.f));   // hidden op+2hp+1
            const u64* w2r0 = &w2d[(op + 2 * hp) * 16];
            const u64* w2r1 = &w2d[(op + 2 * hp + 1) * 16];
#pragma unroll
            for (int o = 0; o < 16; o++) {
                acc2[o] = ffma2(w2r0[o], hv0, acc2[o]);
                acc2[o] = ffma2(w2r1[o], hv1, acc2[o]);
            }
        }
    }
#pragma unroll
    for (int o = 0; o < 16; o++) {
        float a0, a1;
        upk2(acc2[o], a0, a1);
        float2 r = make_float2(fmaxf(a0, 0.f), fmaxf(a1, 0.f));
        *reinterpret_cast<float2*>(&g_ga2[((size_t)b * C4 + o) * HW + p0]) = r;
    }
}

// ---------------- K3: windowed weighted direction stats (separable box sums) ----------------
__global__ __launch_bounds__(256) void k3_cons() {
    __shared__ float sm0[20][20];
    __shared__ float sm1[20][20];
    __shared__ float sm2[20][20];
    __shared__ float h0[20][16];
    __shared__ float h1[20][16];
    __shared__ float h2[20][16];
    int b = blockIdx.z >> 4;
    int cg = blockIdx.z & 15;
    int oy = blockIdx.y * 16, ox = blockIdx.x * 16;
    int tx = threadIdx.x, ty = threadIdx.y;
    int tid = ty * 16 + tx;

    float cons = 0.f;
    for (int cc = 0; cc < 4; cc++) {
        int c = cg * 4 + cc;
        int base = (b * C + c) * HW;
        __syncthreads();
        for (int i = tid; i < 400; i += 256) {
            int r = i / 20, k = i % 20;
            int gh = oy + r - 2, gw = ox + k - 2;
            float m0 = 0.f, m1 = 0.f, m2 = 0.f;
            if ((unsigned)gh < (unsigned)H && (unsigned)gw < (unsigned)Wd) {
                int gi = base + gh * Wd + gw;
                float gx = g_gx[gi], gy = g_gy[gi];
                float mag = sqrtf(gx * gx + gy * gy + EPSF);
                float dir = atan2f(gy, gx);
                m0 = mag;
                m1 = mag * dir;
                m2 = m1 * dir;
            }
            sm0[r][k] = m0;
            sm1[r][k] = m1;
            sm2[r][k] = m2;
        }
        __syncthreads();
        for (int i = tid; i < 320; i += 256) {
            int r = i / 16, k = i % 16;
            float a0 = 0.f, a1 = 0.f, a2 = 0.f;
#pragma unroll
            for (int d = 0; d < 5; d++) {
                a0 += sm0[r][k + d];
                a1 += sm1[r][k + d];
                a2 += sm2[r][k + d];
            }
            h0[r][k] = a0;
            h1[r][k] = a1;
            h2[r][k] = a2;
        }
        __syncthreads();
        float s0 = 0.f, s1 = 0.f, s2 = 0.f;
#pragma unroll
        for (int d = 0; d < 5; d++) {
            s0 += h0[ty + d][tx];
            s1 += h1[ty + d][tx];
            s2 += h2[ty + d][tx];
        }
        float inv = 1.f / (s0 + EPSF);
        float wmean = s1 * inv;
        float wvar = (s2 - 2.f * wmean * s1 + wmean * wmean * s0) * inv;
        wvar = fmaxf(wvar, 0.f);
        cons += 1.f - tanhf(sqrtf(wvar));
    }
    atomicAdd(&g_cons[b * HW + (oy + ty) * Wd + (ox + tx)], cons * (1.f / (float)C));
}

// ---------------- K4: cd branch (3x3 16->16 relu, 1x1 16->1, sigmoid, * cons) ----------------
// 16x8 tiles, 256 blocks x 128 threads
__global__ __launch_bounds__(128) void k4_cd(const float* __restrict__ cw1,
                                             const float* __restrict__ cb1,
                                             const float* __restrict__ cw2,
                                             const float* __restrict__ cb2) {
    __shared__ float sga[C4][10][18];
    __shared__ float w1s[C4 * C4 * 9];
    __shared__ float w2s[C4], b1s[C4];
    __shared__ float b2s_;
    int b = blockIdx.z;
    int oy = blockIdx.y * 8, ox = blockIdx.x * 16;
    int tx = threadIdx.x, ty = threadIdx.y;
    int tid = ty * 16 + tx;

    for (int i = tid; i < C4 * C4 * 9; i += 128) w1s[i] = cw1[i];
    if (tid < C4) { w2s[tid] = cw2[tid]; b1s[tid] = cb1[tid]; }
    if (tid == 0) b2s_ = cb2[0];

    for (int i = tid; i < C4 * 180; i += 128) {
        int ic = i / 180, j = i % 180;
        int r = j / 18, cc = j % 18;
        int gh = oy + r - 1, gw = ox + cc - 1;
        float v = 0.f;
        if ((unsigned)gh < (unsigned)H && (unsigned)gw < (unsigned)Wd)
            v = g_ga2[((size_t)b * C4 + ic) * HW + gh * Wd + gw];
        sga[ic][r][cc] = v;
    }
    __syncthreads();

    float acc[C4];
#pragma unroll
    for (int o = 0; o < C4; o++) acc[o] = b1s[o];

    for (int ic = 0; ic < C4; ic++) {
        float win[9];
#pragma unroll
        for (int dy = 0; dy < 3; dy++)
#pragma unroll
            for (int dx = 0; dx < 3; dx++)
                win[dy * 3 + dx] = sga[ic][ty + dy][tx + dx];
#pragma unroll
        for (int o = 0; o < C4; o++) {
            const float* wp = &w1s[(o * C4 + ic) * 9];
#pragma unroll
            for (int k = 0; k < 9; k++) acc[o] += wp[k] * win[k];
        }
    }
    float s = b2s_;
#pragma unroll
    for (int o = 0; o < C4; o++) s += w2s[o] * fmaxf(acc[o], 0.f);
    float sig = 1.f / (1.f + expf(-s));
    int hw = (oy + ty) * Wd + (ox + tx);
    g_ew[b * HW + hw] = sig * g_cons[b * HW + hw];
}

// ---------------- K5/K6: 3x3 conv 64->64, FFMA2, double-buffered ----------------
// 32x32 spatial tile, 8 oc per block, 2x2 px per thread, all weights preloaded
__global__ __launch_bounds__(256, 2) void k56_conv(const float* __restrict__ wt,
                                                   const float* __restrict__ bias,
                                                   int mode,
                                                   const float* __restrict__ xres,
                                                   const float* __restrict__ alphap,
                                                   float* __restrict__ out) {
    __shared__ __align__(16) u64 ws[8 * 64 * 9];   // (w,w) [(o*64+ic)*9+k]  36.9KB
    __shared__ float sh[2][34][36];                // double-buffered tile   9.8KB

    int b = blockIdx.z >> 3;
    int ocg = blockIdx.z & 7;
    int oy = blockIdx.y * 32, ox = blockIdx.x * 32;
    int tx = threadIdx.x, ty = threadIdx.y;
    int tid = ty * 16 + tx;

    // one-time weight preload (dup-packed)
    for (int i = tid; i < 4608; i += 256) {
        float w = wt[(size_t)ocg * 4608 + i];      // [(ocg*8+o)*64+ic]*9+k
        ws[i] = pk2(w, w);
    }

    // per-thread halo load slots (loop-invariant)
    int goff[5], soff[5];
    bool ld[5], st[5];
#pragma unroll
    for (int j = 0; j < 5; j++) {
        int idx = tid + j * 256;
        st[j] = idx < 1156;
        int rr = idx / 34, cc = idx - rr * 34;
        int gh = oy + rr - 1, gw = ox + cc - 1;
        ld[j] = st[j] && (unsigned)gh < (unsigned)H && (unsigned)gw < (unsigned)Wd;
        goff[j] = gh * Wd + gw;
        soff[j] = rr * 36 + cc;
    }

    const float* inb = (mode == 0) ? (xres + (size_t)b * C * HW)
                                   : (g_ee1 + (size_t)b * C * HW);

    // prologue: stage ic=0
    {
        float* s0 = &sh[0][0][0];
#pragma unroll
        for (int j = 0; j < 5; j++) {
            float v = ld[j] ? __ldg(inb + goff[j]) : 0.f;
            if (st[j]) s0[soff[j]] = v;
        }
    }
    __syncthreads();

    u64 acc[8][2];
#pragma unroll
    for (int o = 0; o < 8; o++) {
        float bv = bias[ocg * 8 + o];
        u64 bp = pk2(bv, bv);
        acc[o][0] = bp;
        acc[o][1] = bp;
    }

    int cur = 0;
#pragma unroll 1
    for (int ic = 0; ic < C; ic++) {
        // prefetch next tile into registers
        float nvv[5];
        if (ic < C - 1) {
            const float* ip = inb + (size_t)(ic + 1) * HW;
#pragma unroll
            for (int j = 0; j < 5; j++)
                nvv[j] = ld[j] ? __ldg(ip + goff[j]) : 0.f;
        }

        // compute from current buffer
        const float* shc = &sh[cur][0][0];
        u64 pr[4][3];
#pragma unroll
        for (int r = 0; r < 4; r++) {
            const float* row = shc + (2 * ty + r) * 36 + 2 * tx;
            float2 p0 = *reinterpret_cast<const float2*>(row);
            float2 p1 = *reinterpret_cast<const float2*>(row + 2);
            pr[r][0] = pk2(p0.x, p0.y);
            pr[r][1] = pk2(p0.y, p1.x);
            pr[r][2] = pk2(p1.x, p1.y);
        }
        const u64* wp = &ws[ic * 9];
#pragma unroll
        for (int o = 0; o < 8; o++) {
            const u64* w9 = wp + o * 576;
#pragma unroll
            for (int ky = 0; ky < 3; ky++) {
#pragma unroll
                for (int kx = 0; kx < 3; kx++) {
                    u64 wv = w9[ky * 3 + kx];
                    acc[o][0] = ffma2(wv, pr[ky][kx], acc[o][0]);
                    acc[o][1] = ffma2(wv, pr[ky + 1][kx], acc[o][1]);
                }
            }
        }

        // commit prefetched tile
        if (ic < C - 1) {
            float* shn = &sh[cur ^ 1][0][0];
#pragma unroll
            for (int j = 0; j < 5; j++)
                if (st[j]) shn[soff[j]] = nvv[j];
        }
        __syncthreads();
        cur ^= 1;
    }

    float alpha = __ldg(alphap);
#pragma unroll
    for (int o = 0; o < 8; o++) {
        int oc = ocg * 8 + o;
#pragma unroll
        for (int r = 0; r < 2; r++) {
            float v0, v1;
            upk2(acc[o][r], v0, v1);
            int h = oy + 2 * ty + r;
            int w0 = ox + 2 * tx;
            size_t oidx = ((size_t)b * C + oc) * HW + h * Wd + w0;
            if (mode == 0) {
                g_ee1[oidx] = fmaxf(v0, 0.f);
                g_ee1[oidx + 1] = fmaxf(v1, 0.f);
            } else {
                float e0 = g_ew[b * HW + h * Wd + w0];
                float e1 = g_ew[b * HW + h * Wd + w0 + 1];
                out[oidx] = xres[oidx] + alpha * e0 * v0;
                out[oidx + 1] = xres[oidx + 1] + alpha * e1 * v1;
            }
        }
    }
}

// ---------------- launch ----------------
extern "C" void kernel_launch(void* const* d_in, const int* in_sizes, int n_in,
                              void* d_out, int out_size) {
    const float* x     = (const float*)d_in[0];
    const float* ga_w1 = (const float*)d_in[3];
    const float* ga_b1 = (const float*)d_in[4];
    const float* ga_w2 = (const float*)d_in[5];
    const float* ga_b2 = (const float*)d_in[6];
    const float* cd_w1 = (const float*)d_in[7];
    const float* cd_b1 = (const float*)d_in[8];
    const float* cd_w2 = (const float*)d_in[9];
    const float* cd_b2 = (const float*)d_in[10];
    const float* ec_w1 = (const float*)d_in[11];
    const float* ec_b1 = (const float*)d_in[12];
    const float* ec_w2 = (const float*)d_in[13];
    const float* ec_b2 = (const float*)d_in[14];
    const float* alpha = (const float*)d_in[15];
    float* out = (float*)d_out;

    k0_zero<<<(B * HW + 255) / 256, 256>>>();
    k1_sobel<<<dim3(8, 8, B * C), dim3(16, 16)>>>(x);
    k2_ga<<<B * HW / 256, 128>>>(ga_w1, ga_b1, ga_w2, ga_b2);
    k3_cons<<<dim3(8, 8, B * 16), dim3(16, 16)>>>();
    k4_cd<<<dim3(8, 16, B), dim3(16, 8)>>>(cd_w1, cd_b1, cd_w2, cd_b2);
    k56_conv<<<dim3(4, 4, B * 8), dim3(16, 16)>>>(ec_w1, ec_b1, 0, x, alpha, out);
    k56_conv<<<dim3(4, 4, B * 8), dim3(16, 16)>>>(ec_w2, ec_b2, 1, x, alpha, out);
}

// round 4
// speedup vs baseline: 4.8235x; 2.2367x over previous
#include <cuda_runtime.h>
#include <cuda_bf16.h>
#include <math.h>

#define B 2
#define C 64
#define C4 16
#define H 128
#define Wd 128
#define HW (H * Wd)
#define EPSF 1e-6f

typedef unsigned long long u64;
typedef unsigned int u32;

// ---------------- scratch (device globals; no allocation allowed) ----------------
__device__ float g_gx[B * C * HW];
__device__ float g_gy[B * C * HW];
__device__ float g_ga2[B * C4 * HW];
__device__ float g_cons[B * HW];
__device__ float g_ew[B * HW];
__device__ __align__(16) __nv_bfloat16 g_xb[B * HW * C];    // x, NHWC bf16
__device__ __align__(16) __nv_bfloat16 g_eeb[B * HW * C];   // relu(conv1), NHWC bf16
__device__ __align__(16) u64 g_wq[2 * 9 * 4 * 64 * 4];      // packed B fragments

// ---------------- packed f32x2 helpers (kept for k2) ----------------
__device__ __forceinline__ u64 pk2(float lo, float hi) {
    u64 r;
    asm("mov.b64 %0, {%1, %2};" : "=l"(r) : "f"(lo), "f"(hi));
    return r;
}
__device__ __forceinline__ void upk2(u64 v, float& lo, float& hi) {
    asm("mov.b64 {%0, %1}, %2;" : "=f"(lo), "=f"(hi) : "l"(v));
}
__device__ __forceinline__ u64 ffma2(u64 a, u64 b, u64 c) {
    u64 d;
    asm("fma.rn.f32x2 %0, %1, %2, %3;" : "=l"(d) : "l"(a), "l"(b), "l"(c));
    return d;
}
__device__ __forceinline__ u32 s2u(const void* p) {
    return (u32)__cvta_generic_to_shared(p);
}

// ---------------- KW: weight repack (B fragments) + zero g_cons ----------------
// g_wq[conv][delta][kc][n][q] u64: lo u32 = bf16x2(W[n][kc*16+2q], [..+1]),
//                                  hi u32 = bf16x2(W[n][kc*16+2q+8], [..+9])
__global__ __launch_bounds__(256) void k_wprep(const float* __restrict__ w1,
                                               const float* __restrict__ w2) {
    int i = blockIdx.x * 256 + threadIdx.x;
    if (i < B * HW) g_cons[i] = 0.f;
    if (i < 2 * 9216) {
        int cv = i / 9216;
        int r = i % 9216;
        int dlt = r / 1024;
        int r2 = r % 1024;
        int kc = r2 / 256;
        int r3 = r2 % 256;
        int n = r3 / 4, q = r3 % 4;
        const float* w = cv ? w2 : w1;
        int ic0 = kc * 16 + 2 * q;
        __nv_bfloat162 lo = __floats2bfloat162_rn(
            w[(n * 64 + ic0) * 9 + dlt], w[(n * 64 + ic0 + 1) * 9 + dlt]);
        __nv_bfloat162 hi = __floats2bfloat162_rn(
            w[(n * 64 + ic0 + 8) * 9 + dlt], w[(n * 64 + ic0 + 9) * 9 + dlt]);
        u64 v = (u64)(*(u32*)&lo) | ((u64)(*(u32*)&hi) << 32);
        g_wq[i] = v;
    }
}

// ---------------- KX: x (NCHW fp32) -> g_xb (NHWC bf16) ----------------
__global__ __launch_bounds__(256) void k_xprep(const float* __restrict__ x) {
    __shared__ float s[64 * 65];
    int b = blockIdx.y;
    int px0 = blockIdx.x * 64;
    int tid = threadIdx.x;
    const float* xb = x + (size_t)b * C * HW;
    for (int i = tid; i < 4096; i += 256) {
        int ic = i >> 6, p = i & 63;
        s[p * 65 + ic] = xb[(size_t)ic * HW + px0 + p];
    }
    __syncthreads();
#pragma unroll
    for (int it = 0; it < 2; it++) {
        int idx = tid + it * 256;      // 0..511
        int p = idx >> 3, seg = idx & 7;
        const float* sp = &s[p * 65 + seg * 8];
        u32 u[4];
#pragma unroll
        for (int k = 0; k < 4; k++) {
            __nv_bfloat162 h2 = __floats2bfloat162_rn(sp[2 * k], sp[2 * k + 1]);
            u[k] = *(u32*)&h2;
        }
        *(uint4*)&g_xb[((size_t)b * HW + px0 + p) * 64 + seg * 8] =
            make_uint4(u[0], u[1], u[2], u[3]);
    }
}

// ---------------- K1: depthwise sobel ----------------
__global__ __launch_bounds__(256) void k1_sobel(const float* __restrict__ x) {
    __shared__ float sx[18][18];
    int plane = blockIdx.z;
    const float* xp = x + (size_t)plane * HW;
    int oy = blockIdx.y * 16, ox = blockIdx.x * 16;
    int tx = threadIdx.x, ty = threadIdx.y;
    int tid = ty * 16 + tx;

    for (int i = tid; i < 18 * 18; i += 256) {
        int r = i / 18, c = i % 18;
        int gh = oy + r - 1, gw = ox + c - 1;
        float v = 0.f;
        if ((unsigned)gh < (unsigned)H && (unsigned)gw < (unsigned)Wd)
            v = xp[gh * Wd + gw];
        sx[r][c] = v;
    }
    __syncthreads();

    float a00 = sx[ty][tx],     a01 = sx[ty][tx + 1],     a02 = sx[ty][tx + 2];
    float a10 = sx[ty + 1][tx],                            a12 = sx[ty + 1][tx + 2];
    float a20 = sx[ty + 2][tx], a21 = sx[ty + 2][tx + 1], a22 = sx[ty + 2][tx + 2];

    float gx = (a02 - a00) + 2.f * (a12 - a10) + (a22 - a20);
    float gy = (a20 - a00) + 2.f * (a21 - a01) + (a22 - a02);

    int idx = plane * HW + (oy + ty) * Wd + (ox + tx);
    g_gx[idx] = gx;
    g_gy[idx] = gy;
}

// ---------------- K2: fused 1x1 chain (128 -> 64 relu -> 16 relu) ----------------
__global__ __launch_bounds__(128) void k2_ga(const float* __restrict__ w1,
                                             const float* __restrict__ b1,
                                             const float* __restrict__ w2,
                                             const float* __restrict__ b2) {
    __shared__ __align__(16) float w1t[128 * 64];
    __shared__ __align__(16) u64 w2d[64 * 16];
    __shared__ __align__(16) float b1t[64];
    __shared__ __align__(16) u64 b2d[16];

    int tid = threadIdx.x;
    for (int i = tid; i < 128 * 64; i += 128) {
        int o = i >> 7, k = i & 127;
        w1t[k * 64 + o] = w1[i];
    }
    for (int i = tid; i < 64 * 16; i += 128) {
        int o2 = i >> 6, h = i & 63;
        float w = w2[i];
        w2d[h * 16 + o2] = pk2(w, w);
    }
    if (tid < 64) b1t[tid] = b1[tid];
    if (tid < 16) b2d[tid] = pk2(b2[tid], b2[tid]);
    __syncthreads();

    int b = blockIdx.x >> 6;
    int p0 = ((blockIdx.x & 63) * 128 + tid) * 2;
    const float* gxp = g_gx + (size_t)b * C * HW + p0;
    const float* gyp = g_gy + (size_t)b * C * HW + p0;

    u64 acc2[16];
#pragma unroll
    for (int o = 0; o < 16; o++) acc2[o] = b2d[o];

#pragma unroll 1
    for (int p = 0; p < 4; p++) {
        int op = p * 16;
        u64 accA[8], accB[8];
        const u64* b1p = reinterpret_cast<const u64*>(&b1t[op]);
#pragma unroll
        for (int q = 0; q < 8; q++) { accA[q] = b1p[q]; accB[q] = b1p[q]; }

        u64 v[8];
#pragma unroll
        for (int j = 0; j < 8; j++)
            v[j] = *reinterpret_cast<const u64*>(gxp + j * HW);

#pragma unroll 1
        for (int g = 0; g < 16; g++) {
            u64 nv[8];
            if (g < 15) {
                const float* s = (g < 7) ? (gxp + (g + 1) * 8 * HW)
                                         : (gyp + ((g + 1) * 8 - 64) * HW);
#pragma unroll
                for (int j = 0; j < 8; j++)
                    nv[j] = *reinterpret_cast<const u64*>(s + j * HW);
            }
#pragma unroll
            for (int j = 0; j < 8; j++) {
                int k = g * 8 + j;
                float v0, v1;
                upk2(v[j], v0, v1);
                u64 va = pk2(v0, v0), vb = pk2(v1, v1);
                const ulonglong2* wr =
                    reinterpret_cast<const ulonglong2*>(&w1t[k * 64 + op]);
#pragma unroll
                for (int q = 0; q < 4; q++) {
                    ulonglong2 wp = wr[q];
                    accA[2 * q]     = ffma2(wp.x, va, accA[2 * q]);
                    accA[2 * q + 1] = ffma2(wp.y, va, accA[2 * q + 1]);
                    accB[2 * q]     = ffma2(wp.x, vb, accB[2 * q]);
                    accB[2 * q + 1] = ffma2(wp.y, vb, accB[2 * q + 1]);
                }
            }
            if (g < 15) {
#pragma unroll
                for (int j = 0; j < 8; j++) v[j] = nv[j];
            }
        }
#pragma unroll
        for (int hp = 0; hp < 8; hp++) {
            float a0, a1, c0, c1;
            upk2(accA[hp], a0, a1);
            upk2(accB[hp], c0, c1);
            u64 hv0 = pk2(fmaxf(a0, 0.f), fmaxf(c0, 0.f));
            u64 hv1 = pk2(fmaxf(a1, 0.f), fmaxf(c1, 0.f));
            const u64* w2r0 = &w2d[(op + 2 * hp) * 16];
            const u64* w2r1 = &w2d[(op + 2 * hp + 1) * 16];
#pragma unroll
            for (int o = 0; o < 16; o++) {
                acc2[o] = ffma2(w2r0[o], hv0, acc2[o]);
                acc2[o] = ffma2(w2r1[o], hv1, acc2[o]);
            }
        }
    }
#pragma unroll
    for (int o = 0; o < 16; o++) {
        float a0, a1;
        upk2(acc2[o], a0, a1);
        float2 r = make_float2(fmaxf(a0, 0.f), fmaxf(a1, 0.f));
        *reinterpret_cast<float2*>(&g_ga2[((size_t)b * C4 + o) * HW + p0]) = r;
    }
}

// ---------------- K3: windowed weighted direction stats ----------------
__global__ __launch_bounds__(256) void k3_cons() {
    __shared__ float sm0[20][20];
    __shared__ float sm1[20][20];
    __shared__ float sm2[20][20];
    __shared__ float h0[20][16];
    __shared__ float h1[20][16];
    __shared__ float h2[20][16];
    int b = blockIdx.z >> 4;
    int cg = blockIdx.z & 15;
    int oy = blockIdx.y * 16, ox = blockIdx.x * 16;
    int tx = threadIdx.x, ty = threadIdx.y;
    int tid = ty * 16 + tx;

    float cons = 0.f;
    for (int cc = 0; cc < 4; cc++) {
        int c = cg * 4 + cc;
        int base = (b * C + c) * HW;
        __syncthreads();
        for (int i = tid; i < 400; i += 256) {
            int r = i / 20, k = i % 20;
            int gh = oy + r - 2, gw = ox + k - 2;
            float m0 = 0.f, m1 = 0.f, m2 = 0.f;
            if ((unsigned)gh < (unsigned)H && (unsigned)gw < (unsigned)Wd) {
                int gi = base + gh * Wd + gw;
                float gx = g_gx[gi], gy = g_gy[gi];
                float mag = sqrtf(gx * gx + gy * gy + EPSF);
                float dir = atan2f(gy, gx);
                m0 = mag;
                m1 = mag * dir;
                m2 = m1 * dir;
            }
            sm0[r][k] = m0;
            sm1[r][k] = m1;
            sm2[r][k] = m2;
        }
        __syncthreads();
        for (int i = tid; i < 320; i += 256) {
            int r = i / 16, k = i % 16;
            float a0 = 0.f, a1 = 0.f, a2 = 0.f;
#pragma unroll
            for (int d = 0; d < 5; d++) {
                a0 += sm0[r][k + d];
                a1 += sm1[r][k + d];
                a2 += sm2[r][k + d];
            }
            h0[r][k] = a0;
            h1[r][k] = a1;
            h2[r][k] = a2;
        }
        __syncthreads();
        float s0 = 0.f, s1 = 0.f, s2 = 0.f;
#pragma unroll
        for (int d = 0; d < 5; d++) {
            s0 += h0[ty + d][tx];
            s1 += h1[ty + d][tx];
            s2 += h2[ty + d][tx];
        }
        float inv = 1.f / (s0 + EPSF);
        float wmean = s1 * inv;
        float wvar = (s2 - 2.f * wmean * s1 + wmean * wmean * s0) * inv;
        wvar = fmaxf(wvar, 0.f);
        cons += 1.f - tanhf(sqrtf(wvar));
    }
    atomicAdd(&g_cons[b * HW + (oy + ty) * Wd + (ox + tx)], cons * (1.f / (float)C));
}

// ---------------- K4: cd branch ----------------
__global__ __launch_bounds__(128) void k4_cd(const float* __restrict__ cw1,
                                             const float* __restrict__ cb1,
                                             const float* __restrict__ cw2,
                                             const float* __restrict__ cb2) {
    __shared__ float sga[C4][10][18];
    __shared__ float w1s[C4 * C4 * 9];
    __shared__ float w2s[C4], b1s[C4];
    __shared__ float b2s_;
    int b = blockIdx.z;
    int oy = blockIdx.y * 8, ox = blockIdx.x * 16;
    int tx = threadIdx.x, ty = threadIdx.y;
    int tid = ty * 16 + tx;

    for (int i = tid; i < C4 * C4 * 9; i += 128) w1s[i] = cw1[i];
    if (tid < C4) { w2s[tid] = cw2[tid]; b1s[tid] = cb1[tid]; }
    if (tid == 0) b2s_ = cb2[0];

    for (int i = tid; i < C4 * 180; i += 128) {
        int ic = i / 180, j = i % 180;
        int r = j / 18, cc = j % 18;
        int gh = oy + r - 1, gw = ox + cc - 1;
        float v = 0.f;
        if ((unsigned)gh < (unsigned)H && (unsigned)gw < (unsigned)Wd)
            v = g_ga2[((size_t)b * C4 + ic) * HW + gh * Wd + gw];
        sga[ic][r][cc] = v;
    }
    __syncthreads();

    float acc[C4];
#pragma unroll
    for (int o = 0; o < C4; o++) acc[o] = b1s[o];

    for (int ic = 0; ic < C4; ic++) {
        float win[9];
#pragma unroll
        for (int dy = 0; dy < 3; dy++)
#pragma unroll
            for (int dx = 0; dx < 3; dx++)
                win[dy * 3 + dx] = sga[ic][ty + dy][tx + dx];
#pragma unroll
        for (int o = 0; o < C4; o++) {
            const float* wp = &w1s[(o * C4 + ic) * 9];
#pragma unroll
            for (int k = 0; k < 9; k++) acc[o] += wp[k] * win[k];
        }
    }
    float s = b2s_;
#pragma unroll
    for (int o = 0; o < C4; o++) s += w2s[o] * fmaxf(acc[o], 0.f);
    float sig = 1.f / (1.f + expf(-s));
    int hw = (oy + ty) * Wd + (ox + tx);
    g_ew[b * HW + hw] = sig * g_cons[b * HW + hw];
}

// ---------------- K5/K6: 3x3 conv 64->64 via bf16 mma.sync implicit GEMM ----------------
// block = 8 warps; px tile 8 rows x 16 cols; all 64 oc; K = 9 taps x 64 ic.
// dynamic smem: Xs (180 px * 128B swizzled NHWC) + Ws (packed B fragments)
#define XS_BYTES 23040
#define WS_BYTES 73728
#define CONV_SMEM (XS_BYTES + WS_BYTES)

extern "C" __global__ void __launch_bounds__(256, 2)
k_conv_mma(int mode, int wqoff, const float* __restrict__ bias,
           const float* __restrict__ xres, const float* __restrict__ alphap,
           float* __restrict__ out) {
    extern __shared__ char dsm[];
    __nv_bfloat16* Xs = (__nv_bfloat16*)dsm;
    u64* Ws = (u64*)(dsm + XS_BYTES);
    __shared__ float sbias[64];

    int tid = threadIdx.x;
    int lane = tid & 31, w = tid >> 5;
    int bcol = blockIdx.x * 16, brow = blockIdx.y * 8;
    int b = blockIdx.z;

    // stage packed weights (linear, coalesced)
    {
        const float4* src = (const float4*)(g_wq + wqoff);
        float4* dst = (float4*)Ws;
        for (int i = tid; i < WS_BYTES / 16; i += 256) dst[i] = src[i];
    }
    if (tid < 64) sbias[tid] = bias[tid];

    // stage input halo: 10x18 px, NHWC bf16, swizzled rows
    const __nv_bfloat16* xb =
        (mode == 0 ? g_xb : g_eeb) + (size_t)b * HW * 64;
    for (int i = tid; i < 180 * 8; i += 256) {
        int p = i >> 3, seg = i & 7;
        int r = p / 18, c = p - r * 18;
        int gh = brow - 1 + r, gc = bcol - 1 + c;
        uint4 v = make_uint4(0, 0, 0, 0);
        if ((unsigned)gh < (unsigned)H && (unsigned)gc < (unsigned)Wd)
            v = *(const uint4*)((const char*)xb +
                                ((size_t)(gh * Wd + gc)) * 128 + seg * 16);
        *(uint4*)((char*)Xs + p * 128 + ((seg * 16) ^ ((p & 7) << 4))) = v;
    }
    __syncthreads();

    float acc[8][4];
#pragma unroll
    for (int nt = 0; nt < 8; nt++)
#pragma unroll
        for (int k = 0; k < 4; k++) acc[nt][k] = 0.f;

    u32 xs_base = s2u(Xs);
    int m = lane & 15;                 // A row (output col)
    int kb = (lane >> 4) << 4;         // k-seg byte offset
    int nq = (lane >> 2) * 4 + (lane & 3);  // B fragment slot

#pragma unroll
    for (int ky = 0; ky < 3; ky++) {
#pragma unroll
        for (int kx = 0; kx < 3; kx++) {
            int p = (w + ky) * 18 + kx + m;
            u32 arow = xs_base + p * 128;
            u32 swz = (u32)((p & 7) << 4);
            const u64* wd = Ws + ((ky * 3 + kx) * 4) * 256 + nq;
#pragma unroll
            for (int kc = 0; kc < 4; kc++) {
                u32 a0, a1, a2, a3;
                u32 addr = arow + ((u32)(kc * 32 + kb) ^ swz);
                asm volatile(
                    "ldmatrix.sync.aligned.m8n8.x4.shared.b16 "
                    "{%0,%1,%2,%3}, [%4];"
                    : "=r"(a0), "=r"(a1), "=r"(a2), "=r"(a3)
                    : "r"(addr));
                const u64* wk = wd + kc * 256;
#pragma unroll
                for (int nt = 0; nt < 8; nt++) {
                    u64 bv = wk[nt * 32];
                    u32 b0 = (u32)bv, b1 = (u32)(bv >> 32);
                    asm volatile(
                        "mma.sync.aligned.m16n8k16.row.col.f32.bf16.bf16.f32 "
                        "{%0,%1,%2,%3}, {%4,%5,%6,%7}, {%8,%9}, {%0,%1,%2,%3};"
                        : "+f"(acc[nt][0]), "+f"(acc[nt][1]),
                          "+f"(acc[nt][2]), "+f"(acc[nt][3])
                        : "r"(a0), "r"(a1), "r"(a2), "r"(a3),
                          "r"(b0), "r"(b1));
                }
            }
        }
    }

    int g = lane >> 2, t = lane & 3;
    if (mode == 0) {
        // relu + bias -> g_eeb NHWC bf16
        int h = brow + w;
        size_t px0 = (size_t)b * HW + h * Wd + bcol + g;
#pragma unroll
        for (int nt = 0; nt < 8; nt++) {
            int oc = nt * 8 + 2 * t;
            float b0f = sbias[oc], b1f = sbias[oc + 1];
            __nv_bfloat162 p01 = __floats2bfloat162_rn(
                fmaxf(acc[nt][0] + b0f, 0.f), fmaxf(acc[nt][1] + b1f, 0.f));
            __nv_bfloat162 p23 = __floats2bfloat162_rn(
                fmaxf(acc[nt][2] + b0f, 0.f), fmaxf(acc[nt][3] + b1f, 0.f));
            *(u32*)&g_eeb[px0 * 64 + oc] = *(u32*)&p01;
            *(u32*)&g_eeb[(px0 + 8) * 64 + oc] = *(u32*)&p23;
        }
    } else {
        // stage [oc][px] in smem, then coalesced NCHW residual write
        float* sep = (float*)dsm;   // 64*132*4 = 33.8KB, reuses Xs/Ws
        __syncthreads();
        int pl0 = w * 16 + g;
#pragma unroll
        for (int nt = 0; nt < 8; nt++) {
            int oc = nt * 8 + 2 * t;
            sep[oc * 132 + pl0]           = acc[nt][0] + sbias[oc];
            sep[(oc + 1) * 132 + pl0]     = acc[nt][1] + sbias[oc + 1];
            sep[oc * 132 + pl0 + 8]       = acc[nt][2] + sbias[oc];
            sep[(oc + 1) * 132 + pl0 + 8] = acc[nt][3] + sbias[oc + 1];
        }
        __syncthreads();
        float alpha = __ldg(alphap);
        for (int i = tid; i < 8192; i += 256) {
            int oc = i >> 7, pxl = i & 127;
            int h = brow + (pxl >> 4), col = bcol + (pxl & 15);
            int gpx = h * Wd + col;
            float v = sep[oc * 132 + pxl];
            float e = g_ew[b * HW + gpx];
            size_t oi = ((size_t)b * C + oc) * HW + gpx;
            out[oi] = xres[oi] + alpha * e * v;
        }
    }
}

// ---------------- launch ----------------
extern "C" void kernel_launch(void* const* d_in, const int* in_sizes, int n_in,
                              void* d_out, int out_size) {
    const float* x     = (const float*)d_in[0];
    const float* ga_w1 = (const float*)d_in[3];
    const float* ga_b1 = (const float*)d_in[4];
    const float* ga_w2 = (const float*)d_in[5];
    const float* ga_b2 = (const float*)d_in[6];
    const float* cd_w1 = (const float*)d_in[7];
    const float* cd_b1 = (const float*)d_in[8];
    const float* cd_w2 = (const float*)d_in[9];
    const float* cd_b2 = (const float*)d_in[10];
    const float* ec_w1 = (const float*)d_in[11];
    const float* ec_b1 = (const float*)d_in[12];
    const float* ec_w2 = (const float*)d_in[13];
    const float* ec_b2 = (const float*)d_in[14];
    const float* alpha = (const float*)d_in[15];
    float* out = (float*)d_out;

    cudaFuncSetAttribute(k_conv_mma,
                         cudaFuncAttributeMaxDynamicSharedMemorySize, CONV_SMEM);

    k_wprep<<<128, 256>>>(ec_w1, ec_w2);                    // also zeroes g_cons
    k_xprep<<<dim3(HW / 64, B), 256>>>(x);
    k1_sobel<<<dim3(8, 8, B * C), dim3(16, 16)>>>(x);
    k2_ga<<<B * HW / 256, 128>>>(ga_w1, ga_b1, ga_w2, ga_b2);
    k3_cons<<<dim3(8, 8, B * 16), dim3(16, 16)>>>();
    k4_cd<<<dim3(8, 16, B), dim3(16, 8)>>>(cd_w1, cd_b1, cd_w2, cd_b2);
    k_conv_mma<<<dim3(8, 16, B), 256, CONV_SMEM>>>(0, 0, ec_b1, x, alpha, out);
    k_conv_mma<<<dim3(8, 16, B), 256, CONV_SMEM>>>(1, 9216, ec_b2, x, alpha, out);
}

// round 5
// speedup vs baseline: 6.0034x; 1.2446x over previous
#include <cuda_runtime.h>
#include <cuda_bf16.h>
#include <math.h>

#define B 2
#define C 64
#define C4 16
#define H 128
#define Wd 128
#define HW (H * Wd)
#define EPSF 1e-6f

typedef unsigned long long u64;
typedef unsigned int u32;

// ---------------- scratch (device globals; no allocation allowed) ----------------
__device__ float g_gx[B * C * HW];
__device__ float g_gy[B * C * HW];
__device__ float g_ga2[B * C4 * HW];
__device__ float g_cons[B * HW];
__device__ float g_ew[B * HW];
__device__ __align__(16) __nv_bfloat16 g_xb[B * HW * C];    // x, NHWC bf16
__device__ __align__(16) __nv_bfloat16 g_eeb[B * HW * C];   // relu(conv1), NHWC bf16
__device__ __align__(16) u64 g_wq[2 * 9 * 4 * 64 * 4];      // conv B fragments
__device__ __align__(16) u64 g_wga1[2048];                  // ga layer1 B fragments
__device__ __align__(16) u64 g_wga2[256];                   // ga layer2 B fragments

__device__ __forceinline__ u32 s2u(const void* p) {
    return (u32)__cvta_generic_to_shared(p);
}

// ---------------- KW: weight repacks + zero g_cons ----------------
__global__ __launch_bounds__(256) void k_wprep(const float* __restrict__ w1,
                                               const float* __restrict__ w2,
                                               const float* __restrict__ gw1,
                                               const float* __restrict__ gw2) {
    int i = blockIdx.x * 256 + threadIdx.x;
    if (i < B * HW) g_cons[i] = 0.f;
    if (i < 2 * 9216) {      // conv weights (ec_w1/ec_w2)
        int cv = i / 9216;
        int r = i % 9216;
        int dlt = r / 1024;
        int r2 = r % 1024;
        int kc = r2 / 256;
        int r3 = r2 % 256;
        int n = r3 / 4, q = r3 % 4;
        const float* w = cv ? w2 : w1;
        int ic0 = kc * 16 + 2 * q;
        __nv_bfloat162 lo = __floats2bfloat162_rn(
            w[(n * 64 + ic0) * 9 + dlt], w[(n * 64 + ic0 + 1) * 9 + dlt]);
        __nv_bfloat162 hi = __floats2bfloat162_rn(
            w[(n * 64 + ic0 + 8) * 9 + dlt], w[(n * 64 + ic0 + 9) * 9 + dlt]);
        g_wq[i] = (u64)(*(u32*)&lo) | ((u64)(*(u32*)&hi) << 32);
    }
    if (i < 2048) {          // ga_w1 [64 x 128]: frag[(kstep*8+nt)*32+lane]
        int kstep = i >> 8;
        int nt = (i >> 5) & 7;
        int l = i & 31;
        int n_oc = nt * 8 + (l >> 2);
        int k0 = kstep * 16 + (l & 3) * 2;
        __nv_bfloat162 lo = __floats2bfloat162_rn(
            gw1[n_oc * 128 + k0], gw1[n_oc * 128 + k0 + 1]);
        __nv_bfloat162 hi = __floats2bfloat162_rn(
            gw1[n_oc * 128 + k0 + 8], gw1[n_oc * 128 + k0 + 9]);
        g_wga1[i] = (u64)(*(u32*)&lo) | ((u64)(*(u32*)&hi) << 32);
    }
    if (i < 256) {           // ga_w2 [16 x 64]: frag[(kstep*2+nt)*32+lane]
        int kstep = i >> 6;
        int nt = (i >> 5) & 1;
        int l = i & 31;
        int n_oc = nt * 8 + (l >> 2);
        int k0 = kstep * 16 + (l & 3) * 2;
        __nv_bfloat162 lo = __floats2bfloat162_rn(
            gw2[n_oc * 64 + k0], gw2[n_oc * 64 + k0 + 1]);
        __nv_bfloat162 hi = __floats2bfloat162_rn(
            gw2[n_oc * 64 + k0 + 8], gw2[n_oc * 64 + k0 + 9]);
        g_wga2[i] = (u64)(*(u32*)&lo) | ((u64)(*(u32*)&hi) << 32);
    }
}

// ---------------- KX: x (NCHW fp32) -> g_xb (NHWC bf16) ----------------
__global__ __launch_bounds__(256) void k_xprep(const float* __restrict__ x) {
    __shared__ float s[64 * 65];
    int b = blockIdx.y;
    int px0 = blockIdx.x * 64;
    int tid = threadIdx.x;
    const float* xb = x + (size_t)b * C * HW;
    for (int i = tid; i < 4096; i += 256) {
        int ic = i >> 6, p = i & 63;
        s[p * 65 + ic] = xb[(size_t)ic * HW + px0 + p];
    }
    __syncthreads();
#pragma unroll
    for (int it = 0; it < 2; it++) {
        int idx = tid + it * 256;
        int p = idx >> 3, seg = idx & 7;
        const float* sp = &s[p * 65 + seg * 8];
        u32 u[4];
#pragma unroll
        for (int k = 0; k < 4; k++) {
            __nv_bfloat162 h2 = __floats2bfloat162_rn(sp[2 * k], sp[2 * k + 1]);
            u[k] = *(u32*)&h2;
        }
        *(uint4*)&g_xb[((size_t)b * HW + px0 + p) * 64 + seg * 8] =
            make_uint4(u[0], u[1], u[2], u[3]);
    }
}

// ---------------- K1: depthwise sobel ----------------
__global__ __launch_bounds__(256) void k1_sobel(const float* __restrict__ x) {
    __shared__ float sx[18][18];
    int plane = blockIdx.z;
    const float* xp = x + (size_t)plane * HW;
    int oy = blockIdx.y * 16, ox = blockIdx.x * 16;
    int tx = threadIdx.x, ty = threadIdx.y;
    int tid = ty * 16 + tx;

    for (int i = tid; i < 18 * 18; i += 256) {
        int r = i / 18, c = i % 18;
        int gh = oy + r - 1, gw = ox + c - 1;
        float v = 0.f;
        if ((unsigned)gh < (unsigned)H && (unsigned)gw < (unsigned)Wd)
            v = xp[gh * Wd + gw];
        sx[r][c] = v;
    }
    __syncthreads();

    float a00 = sx[ty][tx],     a01 = sx[ty][tx + 1],     a02 = sx[ty][tx + 2];
    float a10 = sx[ty + 1][tx],                            a12 = sx[ty + 1][tx + 2];
    float a20 = sx[ty + 2][tx], a21 = sx[ty + 2][tx + 1], a22 = sx[ty + 2][tx + 2];

    float gx = (a02 - a00) + 2.f * (a12 - a10) + (a22 - a20);
    float gy = (a20 - a00) + 2.f * (a21 - a01) + (a22 - a02);

    int idx = plane * HW + (oy + ty) * Wd + (ox + tx);
    g_gx[idx] = gx;
    g_gy[idx] = gy;
}

// ---------------- K2: fused 1x1 chain via bf16 mma (128 -> 64 relu -> 16 relu) ----
// block = 8 warps, 128 px; warp w owns px rows w*16..w*16+15.
#define K2_SMEM 67904
extern "C" __global__ void __launch_bounds__(256, 2)
k2_mma(const float* __restrict__ b1, const float* __restrict__ b2) {
    extern __shared__ char smb[];
    __nv_bfloat16* sIn = (__nv_bfloat16*)smb;            // 2 halves x 128px x 128B
    __nv_bfloat16* sHid = (__nv_bfloat16*)(smb + 32768); // 128px x 128B
    u64* sW1 = (u64*)(smb + 49152);                      // 2048 u64
    u64* sW2 = (u64*)(smb + 65536);                      // 256 u64
    float* sb1 = (float*)(smb + 67584);                  // 64
    float* sb2 = (float*)(smb + 67840);                  // 16

    int tid = threadIdx.x, lane = tid & 31, w = tid >> 5;
    int b = blockIdx.x >> 7;
    int px0 = (blockIdx.x & 127) * 128;

    // stage weight fragments (coalesced)
    {
        const float4* s1 = (const float4*)g_wga1;
        float4* d1 = (float4*)sW1;
        for (int i = tid; i < 1024; i += 256) d1[i] = s1[i];
        if (tid < 128) ((float4*)sW2)[tid] = ((const float4*)g_wga2)[tid];
        if (tid < 64) sb1[tid] = b1[tid];
        if (tid < 16) sb2[tid] = b2[tid];
    }
    // stage input: planar fp32 gx/gy -> px-major bf16 (swizzled)
    const float* gxp = g_gx + (size_t)b * C * HW + px0;
    const float* gyp = g_gy + (size_t)b * C * HW + px0;
    for (int i = tid; i < 8192; i += 256) {
        int cp = i >> 7, px = i & 127;       // channel pair 0..63
        const float* pl = (cp < 32) ? (gxp + (size_t)(cp * 2) * HW)
                                    : (gyp + (size_t)((cp - 32) * 2) * HW);
        __nv_bfloat162 hv = __floats2bfloat162_rn(pl[px], pl[HW + px]);
        int half = cp >> 5, c4 = (cp & 31) * 4;
        *(u32*)((char*)sIn + half * 16384 + px * 128 +
                ((u32)c4 ^ ((u32)(px & 7) << 4))) = *(u32*)&hv;
    }
    __syncthreads();

    int m = lane & 15, kb = (lane >> 4) << 4;
    int p = w * 16 + m;
    u32 swz = (u32)((p & 7) << 4);
    u32 arow = s2u(sIn) + p * 128;

    // layer1: [64oc] = W1[64x128] . v[128]
    float acc[8][4];
#pragma unroll
    for (int nt = 0; nt < 8; nt++)
#pragma unroll
        for (int k = 0; k < 4; k++) acc[nt][k] = 0.f;

#pragma unroll
    for (int kc = 0; kc < 8; kc++) {
        u32 a0, a1, a2, a3;
        u32 addr = arow + (kc >> 2) * 16384 + (((u32)((kc & 3) * 32 + kb)) ^ swz);
        asm volatile(
            "ldmatrix.sync.aligned.m8n8.x4.shared.b16 {%0,%1,%2,%3}, [%4];"
            : "=r"(a0), "=r"(a1), "=r"(a2), "=r"(a3) : "r"(addr));
        const u64* wk = sW1 + (size_t)kc * 256 + lane;
#pragma unroll
        for (int nt = 0; nt < 8; nt++) {
            u64 bv = wk[nt * 32];
            u32 bf0 = (u32)bv, bf1 = (u32)(bv >> 32);
            asm volatile(
                "mma.sync.aligned.m16n8k16.row.col.f32.bf16.bf16.f32 "
                "{%0,%1,%2,%3}, {%4,%5,%6,%7}, {%8,%9}, {%0,%1,%2,%3};"
                : "+f"(acc[nt][0]), "+f"(acc[nt][1]),
                  "+f"(acc[nt][2]), "+f"(acc[nt][3])
                : "r"(a0), "r"(a1), "r"(a2), "r"(a3), "r"(bf0), "r"(bf1));
        }
    }

    // bias + relu -> sHid (px-major bf16, swizzled)
    int rr = lane >> 2, cc0 = (lane & 3) * 2;
    int pr0 = w * 16 + rr, pr1 = pr0 + 8;
#pragma unroll
    for (int nt = 0; nt < 8; nt++) {
        int oc = nt * 8 + cc0;
        float bb0 = sb1[oc], bb1 = sb1[oc + 1];
        __nv_bfloat162 v01 = __floats2bfloat162_rn(
            fmaxf(acc[nt][0] + bb0, 0.f), fmaxf(acc[nt][1] + bb1, 0.f));
        __nv_bfloat162 v23 = __floats2bfloat162_rn(
            fmaxf(acc[nt][2] + bb0, 0.f), fmaxf(acc[nt][3] + bb1, 0.f));
        *(u32*)((char*)sHid + pr0 * 128 +
                ((u32)(oc * 2) ^ ((u32)(pr0 & 7) << 4))) = *(u32*)&v01;
        *(u32*)((char*)sHid + pr1 * 128 +
                ((u32)(oc * 2) ^ ((u32)(pr1 & 7) << 4))) = *(u32*)&v23;
    }
    __syncwarp();

    // layer2: [16oc] = W2[16x64] . h[64]
    float a2c[2][4];
#pragma unroll
    for (int nt = 0; nt < 2; nt++)
#pragma unroll
        for (int k = 0; k < 4; k++) a2c[nt][k] = 0.f;

    u32 hrow = s2u(sHid) + p * 128;
#pragma unroll
    for (int kc = 0; kc < 4; kc++) {
        u32 a0, a1, a2, a3;
        u32 addr = hrow + (((u32)(kc * 32 + kb)) ^ swz);
        asm volatile(
            "ldmatrix.sync.aligned.m8n8.x4.shared.b16 {%0,%1,%2,%3}, [%4];"
            : "=r"(a0), "=r"(a1), "=r"(a2), "=r"(a3) : "r"(addr));
        const u64* wk = sW2 + (size_t)kc * 64 + lane;
#pragma unroll
        for (int nt = 0; nt < 2; nt++) {
            u64 bv = wk[nt * 32];
            u32 bf0 = (u32)bv, bf1 = (u32)(bv >> 32);
            asm volatile(
                "mma.sync.aligned.m16n8k16.row.col.f32.bf16.bf16.f32 "
                "{%0,%1,%2,%3}, {%4,%5,%6,%7}, {%8,%9}, {%0,%1,%2,%3};"
                : "+f"(a2c[nt][0]), "+f"(a2c[nt][1]),
                  "+f"(a2c[nt][2]), "+f"(a2c[nt][3])
                : "r"(a0), "r"(a1), "r"(a2), "r"(a3), "r"(bf0), "r"(bf1));
        }
    }

    // bias + relu -> g_ga2 planar fp32
    int pxg = px0 + w * 16 + rr;
#pragma unroll
    for (int nt = 0; nt < 2; nt++) {
        int oc = nt * 8 + cc0;
        float bb0 = sb2[oc], bb1 = sb2[oc + 1];
        size_t r0 = ((size_t)b * C4 + oc) * HW;
        size_t r1 = ((size_t)b * C4 + oc + 1) * HW;
        g_ga2[r0 + pxg]     = fmaxf(a2c[nt][0] + bb0, 0.f);
        g_ga2[r1 + pxg]     = fmaxf(a2c[nt][1] + bb1, 0.f);
        g_ga2[r0 + pxg + 8] = fmaxf(a2c[nt][2] + bb0, 0.f);
        g_ga2[r1 + pxg + 8] = fmaxf(a2c[nt][3] + bb1, 0.f);
    }
}

// ---------------- K3: windowed weighted direction stats (32x32 tiles) ----------------
__global__ __launch_bounds__(256) void k3_cons() {
    __shared__ float sm0[36][36];
    __shared__ float sm1[36][36];
    __shared__ float sm2[36][36];
    __shared__ float h0[36][32];
    __shared__ float h1[36][32];
    __shared__ float h2[36][32];
    int b = blockIdx.z >> 4;
    int cg = blockIdx.z & 15;
    int oy = blockIdx.y * 32, ox = blockIdx.x * 32;
    int tx = threadIdx.x, ty = threadIdx.y;       // (32, 8)
    int tid = ty * 32 + tx;

    float cons[4] = {0.f, 0.f, 0.f, 0.f};
    for (int cc = 0; cc < 4; cc++) {
        int c = cg * 4 + cc;
        int base = (b * C + c) * HW;
        __syncthreads();
        for (int i = tid; i < 1296; i += 256) {
            int r = i / 36, k = i % 36;
            int gh = oy + r - 2, gw = ox + k - 2;
            float m0 = 0.f, m1 = 0.f, m2 = 0.f;
            if ((unsigned)gh < (unsigned)H && (unsigned)gw < (unsigned)Wd) {
                int gi = base + gh * Wd + gw;
                float gx = g_gx[gi], gy = g_gy[gi];
                float mag = sqrtf(gx * gx + gy * gy + EPSF);
                float dir = atan2f(gy, gx);
                m0 = mag;
                m1 = mag * dir;
                m2 = m1 * dir;
            }
            sm0[r / 36 * 0 + r][k] = m0;   // plain [r][k]
            sm1[r][k] = m1;
            sm2[r][k] = m2;
        }
        __syncthreads();
        for (int i = tid; i < 1152; i += 256) {
            int r = i >> 5, k = i & 31;
            float a0 = 0.f, a1 = 0.f, a2 = 0.f;
#pragma unroll
            for (int d = 0; d < 5; d++) {
                a0 += sm0[r][k + d];
                a1 += sm1[r][k + d];
                a2 += sm2[r][k + d];
            }
            h0[r][k] = a0;
            h1[r][k] = a1;
            h2[r][k] = a2;
        }
        __syncthreads();
#pragma unroll
        for (int j = 0; j < 4; j++) {
            int row = ty + 8 * j;
            float s0 = 0.f, s1 = 0.f, s2 = 0.f;
#pragma unroll
            for (int d = 0; d < 5; d++) {
                s0 += h0[row + d][tx];
                s1 += h1[row + d][tx];
                s2 += h2[row + d][tx];
            }
            float inv = 1.f / (s0 + EPSF);
            float wmean = s1 * inv;
            float wvar = (s2 - 2.f * wmean * s1 + wmean * wmean * s0) * inv;
            wvar = fmaxf(wvar, 0.f);
            cons[j] += 1.f - tanhf(sqrtf(wvar));
        }
    }
#pragma unroll
    for (int j = 0; j < 4; j++)
        atomicAdd(&g_cons[b * HW + (oy + ty + 8 * j) * Wd + (ox + tx)],
                  cons[j] * (1.f / (float)C));
}

// ---------------- K4: cd branch ----------------
__global__ __launch_bounds__(128) void k4_cd(const float* __restrict__ cw1,
                                             const float* __restrict__ cb1,
                                             const float* __restrict__ cw2,
                                             const float* __restrict__ cb2) {
    __shared__ float sga[C4][10][18];
    __shared__ float w1s[C4 * C4 * 9];
    __shared__ float w2s[C4], b1s[C4];
    __shared__ float b2s_;
    int b = blockIdx.z;
    int oy = blockIdx.y * 8, ox = blockIdx.x * 16;
    int tx = threadIdx.x, ty = threadIdx.y;
    int tid = ty * 16 + tx;

    for (int i = tid; i < C4 * C4 * 9; i += 128) w1s[i] = cw1[i];
    if (tid < C4) { w2s[tid] = cw2[tid]; b1s[tid] = cb1[tid]; }
    if (tid == 0) b2s_ = cb2[0];

    for (int i = tid; i < C4 * 180; i += 128) {
        int ic = i / 180, j = i % 180;
        int r = j / 18, cc = j % 18;
        int gh = oy + r - 1, gw = ox + cc - 1;
        float v = 0.f;
        if ((unsigned)gh < (unsigned)H && (unsigned)gw < (unsigned)Wd)
            v = g_ga2[((size_t)b * C4 + ic) * HW + gh * Wd + gw];
        sga[ic][r][cc] = v;
    }
    __syncthreads();

    float acc[C4];
#pragma unroll
    for (int o = 0; o < C4; o++) acc[o] = b1s[o];

    for (int ic = 0; ic < C4; ic++) {
        float win[9];
#pragma unroll
        for (int dy = 0; dy < 3; dy++)
#pragma unroll
            for (int dx = 0; dx < 3; dx++)
                win[dy * 3 + dx] = sga[ic][ty + dy][tx + dx];
#pragma unroll
        for (int o = 0; o < C4; o++) {
            const float* wp = &w1s[(o * C4 + ic) * 9];
#pragma unroll
            for (int k = 0; k < 9; k++) acc[o] += wp[k] * win[k];
        }
    }
    float s = b2s_;
#pragma unroll
    for (int o = 0; o < C4; o++) s += w2s[o] * fmaxf(acc[o], 0.f);
    float sig = 1.f / (1.f + expf(-s));
    int hw = (oy + ty) * Wd + (ox + tx);
    g_ew[b * HW + hw] = sig * g_cons[b * HW + hw];
}

// ---------------- K5/K6: 3x3 conv 64->64 via bf16 mma.sync implicit GEMM ----------------
#define XS_BYTES 23040
#define WS_BYTES 73728
#define CONV_SMEM (XS_BYTES + WS_BYTES)

extern "C" __global__ void __launch_bounds__(256, 2)
k_conv_mma(int mode, int wqoff, const float* __restrict__ bias,
           const float* __restrict__ xres, const float* __restrict__ alphap,
           float* __restrict__ out) {
    extern __shared__ char dsm[];
    __nv_bfloat16* Xs = (__nv_bfloat16*)dsm;
    u64* Ws = (u64*)(dsm + XS_BYTES);
    __shared__ float sbias[64];

    int tid = threadIdx.x;
    int lane = tid & 31, w = tid >> 5;
    int bcol = blockIdx.x * 16, brow = blockIdx.y * 8;
    int b = blockIdx.z;

    {
        const float4* src = (const float4*)(g_wq + wqoff);
        float4* dst = (float4*)Ws;
        for (int i = tid; i < WS_BYTES / 16; i += 256) dst[i] = src[i];
    }
    if (tid < 64) sbias[tid] = bias[tid];

    const __nv_bfloat16* xb =
        (mode == 0 ? g_xb : g_eeb) + (size_t)b * HW * 64;
    for (int i = tid; i < 180 * 8; i += 256) {
        int p = i >> 3, seg = i & 7;
        int r = p / 18, c = p - r * 18;
        int gh = brow - 1 + r, gc = bcol - 1 + c;
        uint4 v = make_uint4(0, 0, 0, 0);
        if ((unsigned)gh < (unsigned)H && (unsigned)gc < (unsigned)Wd)
            v = *(const uint4*)((const char*)xb +
                                ((size_t)(gh * Wd + gc)) * 128 + seg * 16);
        *(uint4*)((char*)Xs + p * 128 + ((seg * 16) ^ ((p & 7) << 4))) = v;
    }
    __syncthreads();

    float acc[8][4];
#pragma unroll
    for (int nt = 0; nt < 8; nt++)
#pragma unroll
        for (int k = 0; k < 4; k++) acc[nt][k] = 0.f;

    u32 xs_base = s2u(Xs);
    int m = lane & 15;
    int kb = (lane >> 4) << 4;
    int nq = (lane >> 2) * 4 + (lane & 3);

#pragma unroll
    for (int ky = 0; ky < 3; ky++) {
#pragma unroll
        for (int kx = 0; kx < 3; kx++) {
            int p = (w + ky) * 18 + kx + m;
            u32 arow = xs_base + p * 128;
            u32 swz = (u32)((p & 7) << 4);
            const u64* wd = Ws + ((ky * 3 + kx) * 4) * 256 + nq;
#pragma unroll
            for (int kc = 0; kc < 4; kc++) {
                u32 a0, a1, a2, a3;
                u32 addr = arow + ((u32)(kc * 32 + kb) ^ swz);
                asm volatile(
                    "ldmatrix.sync.aligned.m8n8.x4.shared.b16 "
                    "{%0,%1,%2,%3}, [%4];"
                    : "=r"(a0), "=r"(a1), "=r"(a2), "=r"(a3)
                    : "r"(addr));
                const u64* wk = wd + kc * 256;
#pragma unroll
                for (int nt = 0; nt < 8; nt++) {
                    u64 bv = wk[nt * 32];
                    u32 b0 = (u32)bv, b1 = (u32)(bv >> 32);
                    asm volatile(
                        "mma.sync.aligned.m16n8k16.row.col.f32.bf16.bf16.f32 "
                        "{%0,%1,%2,%3}, {%4,%5,%6,%7}, {%8,%9}, {%0,%1,%2,%3};"
                        : "+f"(acc[nt][0]), "+f"(acc[nt][1]),
                          "+f"(acc[nt][2]), "+f"(acc[nt][3])
                        : "r"(a0), "r"(a1), "r"(a2), "r"(a3),
                          "r"(b0), "r"(b1));
                }
            }
        }
    }

    int g = lane >> 2, t = lane & 3;
    if (mode == 0) {
        int h = brow + w;
        size_t px0 = (size_t)b * HW + h * Wd + bcol + g;
#pragma unroll
        for (int nt = 0; nt < 8; nt++) {
            int oc = nt * 8 + 2 * t;
            float b0f = sbias[oc], b1f = sbias[oc + 1];
            __nv_bfloat162 p01 = __floats2bfloat162_rn(
                fmaxf(acc[nt][0] + b0f, 0.f), fmaxf(acc[nt][1] + b1f, 0.f));
            __nv_bfloat162 p23 = __floats2bfloat162_rn(
                fmaxf(acc[nt][2] + b0f, 0.f), fmaxf(acc[nt][3] + b1f, 0.f));
            *(u32*)&g_eeb[px0 * 64 + oc] = *(u32*)&p01;
            *(u32*)&g_eeb[(px0 + 8) * 64 + oc] = *(u32*)&p23;
        }
    } else {
        float* sep = (float*)dsm;
        __syncthreads();
        int pl0 = w * 16 + g;
#pragma unroll
        for (int nt = 0; nt < 8; nt++) {
            int oc = nt * 8 + 2 * t;
            sep[oc * 132 + pl0]           = acc[nt][0] + sbias[oc];
            sep[(oc + 1) * 132 + pl0]     = acc[nt][1] + sbias[oc + 1];
            sep[oc * 132 + pl0 + 8]       = acc[nt][2] + sbias[oc];
            sep[(oc + 1) * 132 + pl0 + 8] = acc[nt][3] + sbias[oc + 1];
        }
        __syncthreads();
        float alpha = __ldg(alphap);
        for (int i = tid; i < 8192; i += 256) {
            int oc = i >> 7, pxl = i & 127;
            int h = brow + (pxl >> 4), col = bcol + (pxl & 15);
            int gpx = h * Wd + col;
            float v = sep[oc * 132 + pxl];
            float e = g_ew[b * HW + gpx];
            size_t oi = ((size_t)b * C + oc) * HW + gpx;
            out[oi] = xres[oi] + alpha * e * v;
        }
    }
}

// ---------------- launch ----------------
extern "C" void kernel_launch(void* const* d_in, const int* in_sizes, int n_in,
                              void* d_out, int out_size) {
    const float* x     = (const float*)d_in[0];
    const float* ga_w1 = (const float*)d_in[3];
    const float* ga_b1 = (const float*)d_in[4];
    const float* ga_w2 = (const float*)d_in[5];
    const float* ga_b2 = (const float*)d_in[6];
    const float* cd_w1 = (const float*)d_in[7];
    const float* cd_b1 = (const float*)d_in[8];
    const float* cd_w2 = (const float*)d_in[9];
    const float* cd_b2 = (const float*)d_in[10];
    const float* ec_w1 = (const float*)d_in[11];
    const float* ec_b1 = (const float*)d_in[12];
    const float* ec_w2 = (const float*)d_in[13];
    const float* ec_b2 = (const float*)d_in[14];
    const float* alpha = (const float*)d_in[15];
    float* out = (float*)d_out;

    cudaFuncSetAttribute(k_conv_mma,
                         cudaFuncAttributeMaxDynamicSharedMemorySize, CONV_SMEM);
    cudaFuncSetAttribute(k2_mma,
                         cudaFuncAttributeMaxDynamicSharedMemorySize, K2_SMEM);

    k_wprep<<<128, 256>>>(ec_w1, ec_w2, ga_w1, ga_w2);
    k_xprep<<<dim3(HW / 64, B), 256>>>(x);
    k1_sobel<<<dim3(8, 8, B * C), dim3(16, 16)>>>(x);
    k2_mma<<<B * HW / 128, 256, K2_SMEM>>>(ga_b1, ga_b2);
    k3_cons<<<dim3(4, 4, B * 16), dim3(32, 8)>>>();
    k4_cd<<<dim3(8, 16, B), dim3(16, 8)>>>(cd_w1, cd_b1, cd_w2, cd_b2);
    k_conv_mma<<<dim3(8, 16, B), 256, CONV_SMEM>>>(0, 0, ec_b1, x, alpha, out);
    k_conv_mma<<<dim3(8, 16, B), 256, CONV_SMEM>>>(1, 9216, ec_b2, x, alpha, out);
}

// round 6
// speedup vs baseline: 6.8170x; 1.1355x over previous
#include <cuda_runtime.h>
#include <cuda_bf16.h>
#include <math.h>

#define B 2
#define C 64
#define C4 16
#define H 128
#define Wd 128
#define HW (H * Wd)
#define EPSF 1e-6f

typedef unsigned long long u64;
typedef unsigned int u32;

// ---------------- scratch (device globals; no allocation allowed) ----------------
__device__ float g_gx[B * C * HW];
__device__ float g_gy[B * C * HW];
__device__ float g_ga2[B * C4 * HW];
__device__ float g_cons[B * HW];
__device__ float g_ew[B * HW];
__device__ __align__(16) __nv_bfloat16 g_xb[B * HW * C];    // x, NHWC bf16
__device__ __align__(16) __nv_bfloat16 g_eeb[B * HW * C];   // relu(conv1), NHWC bf16
__device__ __align__(16) u64 g_wq[2 * 9 * 4 * 64 * 4];      // conv B fragments
__device__ __align__(16) u64 g_wga1[2048];                  // ga layer1 B fragments
__device__ __align__(16) u64 g_wga2[256];                   // ga layer2 B fragments

__device__ __forceinline__ u32 s2u(const void* p) {
    return (u32)__cvta_generic_to_shared(p);
}

// ---------------- fast math (approx, errors << 1e-3 tolerance) ----------------
__device__ __forceinline__ float fsqrt_ap(float v) {
    float r; asm("sqrt.approx.f32 %0, %1;" : "=f"(r) : "f"(v)); return r;
}
__device__ __forceinline__ float ftanh_ap(float v) {
    float r; asm("tanh.approx.f32 %0, %1;" : "=f"(r) : "f"(v)); return r;
}
__device__ __forceinline__ float frcp_ap(float v) {
    float r; asm("rcp.approx.f32 %0, %1;" : "=f"(r) : "f"(v)); return r;
}
__device__ __forceinline__ float fatan2_ap(float y, float x) {
    float ax = fabsf(x), ay = fabsf(y);
    float mx = fmaxf(ax, ay), mn = fminf(ax, ay);
    float z = __fdividef(mn, fmaxf(mx, 1e-30f));
    float s = z * z;
    float p = fmaf(s, -0.0117212f, 0.0526533f);
    p = fmaf(s, p, -0.1164329f);
    p = fmaf(s, p, 0.1935435f);
    p = fmaf(s, p, -0.3326235f);
    p = fmaf(s, p, 0.9999773f);
    float r = p * z;
    if (ay > ax) r = 1.57079632679f - r;
    if (x < 0.f) r = 3.14159265359f - r;
    return copysignf(r, y);
}

// ---------------- K_PRE: weight packs + g_cons zero + x->NHWC bf16 + sobel ----
// grid.x: [0,128) wprep, [128,640) xprep, [640,2688) sobel 32x32 tiles
__global__ __launch_bounds__(256) void k_pre(const float* __restrict__ x,
                                             const float* __restrict__ w1,
                                             const float* __restrict__ w2,
                                             const float* __restrict__ gw1,
                                             const float* __restrict__ gw2) {
    __shared__ __align__(16) char sm[16640];
    int bx = blockIdx.x, tid = threadIdx.x;

    if (bx < 128) {
        int i = bx * 256 + tid;
        g_cons[i] = 0.f;
        if (i < 2 * 9216) {      // conv weights
            int cv = i / 9216;
            int r = i % 9216;
            int dlt = r / 1024;
            int r2 = r % 1024;
            int kc = r2 / 256;
            int r3 = r2 % 256;
            int n = r3 / 4, q = r3 % 4;
            const float* w = cv ? w2 : w1;
            int ic0 = kc * 16 + 2 * q;
            __nv_bfloat162 lo = __floats2bfloat162_rn(
                w[(n * 64 + ic0) * 9 + dlt], w[(n * 64 + ic0 + 1) * 9 + dlt]);
            __nv_bfloat162 hi = __floats2bfloat162_rn(
                w[(n * 64 + ic0 + 8) * 9 + dlt], w[(n * 64 + ic0 + 9) * 9 + dlt]);
            g_wq[i] = (u64)(*(u32*)&lo) | ((u64)(*(u32*)&hi) << 32);
        }
        if (i < 2048) {          // ga_w1 fragments
            int kstep = i >> 8;
            int nt = (i >> 5) & 7;
            int l = i & 31;
            int n_oc = nt * 8 + (l >> 2);
            int k0 = kstep * 16 + (l & 3) * 2;
            __nv_bfloat162 lo = __floats2bfloat162_rn(
                gw1[n_oc * 128 + k0], gw1[n_oc * 128 + k0 + 1]);
            __nv_bfloat162 hi = __floats2bfloat162_rn(
                gw1[n_oc * 128 + k0 + 8], gw1[n_oc * 128 + k0 + 9]);
            g_wga1[i] = (u64)(*(u32*)&lo) | ((u64)(*(u32*)&hi) << 32);
        }
        if (i < 256) {           // ga_w2 fragments
            int kstep = i >> 6;
            int nt = (i >> 5) & 1;
            int l = i & 31;
            int n_oc = nt * 8 + (l >> 2);
            int k0 = kstep * 16 + (l & 3) * 2;
            __nv_bfloat162 lo = __floats2bfloat162_rn(
                gw2[n_oc * 64 + k0], gw2[n_oc * 64 + k0 + 1]);
            __nv_bfloat162 hi = __floats2bfloat162_rn(
                gw2[n_oc * 64 + k0 + 8], gw2[n_oc * 64 + k0 + 9]);
            g_wga2[i] = (u64)(*(u32*)&lo) | ((u64)(*(u32*)&hi) << 32);
        }
    } else if (bx < 640) {
        // x (NCHW fp32) -> g_xb (NHWC bf16), 64 px per block
        int bb = bx - 128;
        int b = bb >> 8;
        int px0 = (bb & 255) * 64;
        float* s = (float*)sm;   // [64 px][65]
        const float* xb = x + (size_t)b * C * HW;
        for (int i = tid; i < 4096; i += 256) {
            int ic = i >> 6, p = i & 63;
            s[p * 65 + ic] = xb[(size_t)ic * HW + px0 + p];
        }
        __syncthreads();
#pragma unroll
        for (int it = 0; it < 2; it++) {
            int idx = tid + it * 256;
            int p = idx >> 3, seg = idx & 7;
            const float* sp = &s[p * 65 + seg * 8];
            u32 u[4];
#pragma unroll
            for (int k = 0; k < 4; k++) {
                __nv_bfloat162 h2 = __floats2bfloat162_rn(sp[2 * k], sp[2 * k + 1]);
                u[k] = *(u32*)&h2;
            }
            *(uint4*)&g_xb[((size_t)b * HW + px0 + p) * 64 + seg * 8] =
                make_uint4(u[0], u[1], u[2], u[3]);
        }
    } else {
        // depthwise sobel, 32x32 tile per block
        int z = bx - 640;
        int plane = z >> 4;
        int oy = ((z >> 2) & 3) * 32, ox = (z & 3) * 32;
        float* sx = (float*)sm;  // [34*34]
        const float* xp = x + (size_t)plane * HW;
        for (int i = tid; i < 1156; i += 256) {
            int r = i / 34, c = i - r * 34;
            int gh = oy + r - 1, gw = ox + c - 1;
            float v = 0.f;
            if ((unsigned)gh < (unsigned)H && (unsigned)gw < (unsigned)Wd)
                v = xp[gh * Wd + gw];
            sx[r * 34 + c] = v;
        }
        __syncthreads();
#pragma unroll
        for (int k = 0; k < 4; k++) {
            int px = tid + k * 256;
            int row = px >> 5, col = px & 31;
            const float* s0 = sx + row * 34 + col;
            float a00 = s0[0],  a01 = s0[1],  a02 = s0[2];
            float a10 = s0[34],               a12 = s0[36];
            float a20 = s0[68], a21 = s0[69], a22 = s0[70];
            float gx = (a02 - a00) + 2.f * (a12 - a10) + (a22 - a20);
            float gy = (a20 - a00) + 2.f * (a21 - a01) + (a22 - a02);
            int idx = plane * HW + (oy + row) * Wd + ox + col;
            g_gx[idx] = gx;
            g_gy[idx] = gy;
        }
    }
}

// ---------------- K2: fused 1x1 chain via bf16 mma (128 -> 64 relu -> 16 relu) ----
// 4 warps, 64 px per block, 512 blocks.
#define K2_SMEM 43328
extern "C" __global__ void __launch_bounds__(128)
k2_mma(const float* __restrict__ b1, const float* __restrict__ b2) {
    extern __shared__ char smb[];
    __nv_bfloat16* sIn = (__nv_bfloat16*)smb;            // 2 halves x 64px x 128B
    __nv_bfloat16* sHid = (__nv_bfloat16*)(smb + 16384); // 64px x 128B
    u64* sW1 = (u64*)(smb + 24576);                      // 2048 u64
    u64* sW2 = (u64*)(smb + 40960);                      // 256 u64
    float* sb1 = (float*)(smb + 43008);                  // 64
    float* sb2 = (float*)(smb + 43264);                  // 16

    int tid = threadIdx.x, lane = tid & 31, w = tid >> 5;
    int b = blockIdx.x >> 8;
    int px0 = (blockIdx.x & 255) * 64;

    {
        const float4* s1 = (const float4*)g_wga1;
        float4* d1 = (float4*)sW1;
#pragma unroll
        for (int i = tid; i < 1024; i += 128) d1[i] = s1[i];
        ((float4*)sW2)[tid] = ((const float4*)g_wga2)[tid];
        if (tid < 64) sb1[tid] = b1[tid];
        if (tid < 16) sb2[tid] = b2[tid];
    }
    // stage input: planar fp32 gx/gy -> px-major bf16 (swizzled)
    const float* gxp = g_gx + (size_t)b * C * HW + px0;
    const float* gyp = g_gy + (size_t)b * C * HW + px0;
    for (int i = tid; i < 4096; i += 128) {
        int cp = i >> 6, px = i & 63;
        const float* pl = (cp < 32) ? (gxp + (size_t)(cp * 2) * HW)
                                    : (gyp + (size_t)((cp - 32) * 2) * HW);
        __nv_bfloat162 hv = __floats2bfloat162_rn(pl[px], pl[HW + px]);
        int half = cp >> 5, c4 = (cp & 31) * 4;
        *(u32*)((char*)sIn + half * 8192 + px * 128 +
                ((u32)c4 ^ ((u32)(px & 7) << 4))) = *(u32*)&hv;
    }
    __syncthreads();

    int m = lane & 15, kb = (lane >> 4) << 4;
    int p = w * 16 + m;
    u32 swz = (u32)((p & 7) << 4);
    u32 arow = s2u(sIn) + p * 128;

    float acc[8][4];
#pragma unroll
    for (int nt = 0; nt < 8; nt++)
#pragma unroll
        for (int k = 0; k < 4; k++) acc[nt][k] = 0.f;

#pragma unroll
    for (int kc = 0; kc < 8; kc++) {
        u32 a0, a1, a2, a3;
        u32 addr = arow + (kc >> 2) * 8192 + (((u32)((kc & 3) * 32 + kb)) ^ swz);
        asm volatile(
            "ldmatrix.sync.aligned.m8n8.x4.shared.b16 {%0,%1,%2,%3}, [%4];"
            : "=r"(a0), "=r"(a1), "=r"(a2), "=r"(a3) : "r"(addr));
        const u64* wk = sW1 + (size_t)kc * 256 + lane;
#pragma unroll
        for (int nt = 0; nt < 8; nt++) {
            u64 bv = wk[nt * 32];
            u32 bf0 = (u32)bv, bf1 = (u32)(bv >> 32);
            asm volatile(
                "mma.sync.aligned.m16n8k16.row.col.f32.bf16.bf16.f32 "
                "{%0,%1,%2,%3}, {%4,%5,%6,%7}, {%8,%9}, {%0,%1,%2,%3};"
                : "+f"(acc[nt][0]), "+f"(acc[nt][1]),
                  "+f"(acc[nt][2]), "+f"(acc[nt][3])
                : "r"(a0), "r"(a1), "r"(a2), "r"(a3), "r"(bf0), "r"(bf1));
        }
    }

    // bias + relu -> sHid (px-major bf16, swizzled)
    int rr = lane >> 2, cc0 = (lane & 3) * 2;
    int pr0 = w * 16 + rr, pr1 = pr0 + 8;
#pragma unroll
    for (int nt = 0; nt < 8; nt++) {
        int oc = nt * 8 + cc0;
        float bb0 = sb1[oc], bb1 = sb1[oc + 1];
        __nv_bfloat162 v01 = __floats2bfloat162_rn(
            fmaxf(acc[nt][0] + bb0, 0.f), fmaxf(acc[nt][1] + bb1, 0.f));
        __nv_bfloat162 v23 = __floats2bfloat162_rn(
            fmaxf(acc[nt][2] + bb0, 0.f), fmaxf(acc[nt][3] + bb1, 0.f));
        *(u32*)((char*)sHid + pr0 * 128 +
                ((u32)(oc * 2) ^ ((u32)(pr0 & 7) << 4))) = *(u32*)&v01;
        *(u32*)((char*)sHid + pr1 * 128 +
                ((u32)(oc * 2) ^ ((u32)(pr1 & 7) << 4))) = *(u32*)&v23;
    }
    __syncwarp();

    // layer2: [16oc] = W2[16x64] . h[64]
    float a2c[2][4];
#pragma unroll
    for (int nt = 0; nt < 2; nt++)
#pragma unroll
        for (int k = 0; k < 4; k++) a2c[nt][k] = 0.f;

    u32 hrow = s2u(sHid) + p * 128;
#pragma unroll
    for (int kc = 0; kc < 4; kc++) {
        u32 a0, a1, a2, a3;
        u32 addr = hrow + (((u32)(kc * 32 + kb)) ^ swz);
        asm volatile(
            "ldmatrix.sync.aligned.m8n8.x4.shared.b16 {%0,%1,%2,%3}, [%4];"
            : "=r"(a0), "=r"(a1), "=r"(a2), "=r"(a3) : "r"(addr));
        const u64* wk = sW2 + (size_t)kc * 64 + lane;
#pragma unroll
        for (int nt = 0; nt < 2; nt++) {
            u64 bv = wk[nt * 32];
            u32 bf0 = (u32)bv, bf1 = (u32)(bv >> 32);
            asm volatile(
                "mma.sync.aligned.m16n8k16.row.col.f32.bf16.bf16.f32 "
                "{%0,%1,%2,%3}, {%4,%5,%6,%7}, {%8,%9}, {%0,%1,%2,%3};"
                : "+f"(a2c[nt][0]), "+f"(a2c[nt][1]),
                  "+f"(a2c[nt][2]), "+f"(a2c[nt][3])
                : "r"(a0), "r"(a1), "r"(a2), "r"(a3), "r"(bf0), "r"(bf1));
        }
    }

    int pxg = px0 + w * 16 + rr;
#pragma unroll
    for (int nt = 0; nt < 2; nt++) {
        int oc = nt * 8 + cc0;
        float bb0 = sb2[oc], bb1 = sb2[oc + 1];
        size_t r0 = ((size_t)b * C4 + oc) * HW;
        size_t r1 = ((size_t)b * C4 + oc + 1) * HW;
        g_ga2[r0 + pxg]     = fmaxf(a2c[nt][0] + bb0, 0.f);
        g_ga2[r1 + pxg]     = fmaxf(a2c[nt][1] + bb1, 0.f);
        g_ga2[r0 + pxg + 8] = fmaxf(a2c[nt][2] + bb0, 0.f);
        g_ga2[r1 + pxg + 8] = fmaxf(a2c[nt][3] + bb1, 0.f);
    }
}

// ---------------- K3: windowed weighted direction stats (32x32, fast math) -----
__global__ __launch_bounds__(256) void k3_cons() {
    __shared__ float sm0[36][36];
    __shared__ float sm1[36][36];
    __shared__ float sm2[36][36];
    __shared__ float h0[36][32];
    __shared__ float h1[36][32];
    __shared__ float h2[36][32];
    int b = blockIdx.z >> 4;
    int cg = blockIdx.z & 15;
    int oy = blockIdx.y * 32, ox = blockIdx.x * 32;
    int tx = threadIdx.x, ty = threadIdx.y;       // (32, 8)
    int tid = ty * 32 + tx;

    float cons[4] = {0.f, 0.f, 0.f, 0.f};
    for (int cc = 0; cc < 4; cc++) {
        int c = cg * 4 + cc;
        int base = (b * C + c) * HW;
        __syncthreads();
        for (int i = tid; i < 1296; i += 256) {
            int r = i / 36, k = i % 36;
            int gh = oy + r - 2, gw = ox + k - 2;
            float m0 = 0.f, m1 = 0.f, m2 = 0.f;
            if ((unsigned)gh < (unsigned)H && (unsigned)gw < (unsigned)Wd) {
                int gi = base + gh * Wd + gw;
                float gx = g_gx[gi], gy = g_gy[gi];
                float mag = fsqrt_ap(gx * gx + gy * gy + EPSF);
                float dir = fatan2_ap(gy, gx);
                m0 = mag;
                m1 = mag * dir;
                m2 = m1 * dir;
            }
            sm0[r][k] = m0;
            sm1[r][k] = m1;
            sm2[r][k] = m2;
        }
        __syncthreads();
        for (int i = tid; i < 1152; i += 256) {
            int r = i >> 5, k = i & 31;
            float a0 = 0.f, a1 = 0.f, a2 = 0.f;
#pragma unroll
            for (int d = 0; d < 5; d++) {
                a0 += sm0[r][k + d];
                a1 += sm1[r][k + d];
                a2 += sm2[r][k + d];
            }
            h0[r][k] = a0;
            h1[r][k] = a1;
            h2[r][k] = a2;
        }
        __syncthreads();
#pragma unroll
        for (int j = 0; j < 4; j++) {
            int row = ty + 8 * j;
            float s0 = 0.f, s1 = 0.f, s2 = 0.f;
#pragma unroll
            for (int d = 0; d < 5; d++) {
                s0 += h0[row + d][tx];
                s1 += h1[row + d][tx];
                s2 += h2[row + d][tx];
            }
            float inv = frcp_ap(s0 + EPSF);
            float wmean = s1 * inv;
            float wvar = (s2 - 2.f * wmean * s1 + wmean * wmean * s0) * inv;
            wvar = fmaxf(wvar, 0.f);
            cons[j] += 1.f - ftanh_ap(fsqrt_ap(wvar));
        }
    }
#pragma unroll
    for (int j = 0; j < 4; j++)
        atomicAdd(&g_cons[b * HW + (oy + ty + 8 * j) * Wd + (ox + tx)],
                  cons[j] * (1.f / (float)C));
}

// ---------------- K4: cd branch ----------------
__global__ __launch_bounds__(128) void k4_cd(const float* __restrict__ cw1,
                                             const float* __restrict__ cb1,
                                             const float* __restrict__ cw2,
                                             const float* __restrict__ cb2) {
    __shared__ float sga[C4][10][18];
    __shared__ float w1s[C4 * C4 * 9];
    __shared__ float w2s[C4], b1s[C4];
    __shared__ float b2s_;
    int b = blockIdx.z;
    int oy = blockIdx.y * 8, ox = blockIdx.x * 16;
    int tx = threadIdx.x, ty = threadIdx.y;
    int tid = ty * 16 + tx;

    for (int i = tid; i < C4 * C4 * 9; i += 128) w1s[i] = cw1[i];
    if (tid < C4) { w2s[tid] = cw2[tid]; b1s[tid] = cb1[tid]; }
    if (tid == 0) b2s_ = cb2[0];

    for (int i = tid; i < C4 * 180; i += 128) {
        int ic = i / 180, j = i % 180;
        int r = j / 18, cc = j % 18;
        int gh = oy + r - 1, gw = ox + cc - 1;
        float v = 0.f;
        if ((unsigned)gh < (unsigned)H && (unsigned)gw < (unsigned)Wd)
            v = g_ga2[((size_t)b * C4 + ic) * HW + gh * Wd + gw];
        sga[ic][r][cc] = v;
    }
    __syncthreads();

    float acc[C4];
#pragma unroll
    for (int o = 0; o < C4; o++) acc[o] = b1s[o];

    for (int ic = 0; ic < C4; ic++) {
        float win[9];
#pragma unroll
        for (int dy = 0; dy < 3; dy++)
#pragma unroll
            for (int dx = 0; dx < 3; dx++)
                win[dy * 3 + dx] = sga[ic][ty + dy][tx + dx];
#pragma unroll
        for (int o = 0; o < C4; o++) {
            const float* wp = &w1s[(o * C4 + ic) * 9];
#pragma unroll
            for (int k = 0; k < 9; k++) acc[o] += wp[k] * win[k];
        }
    }
    float s = b2s_;
#pragma unroll
    for (int o = 0; o < C4; o++) s += w2s[o] * fmaxf(acc[o], 0.f);
    float sig = frcp_ap(1.f + __expf(-s));
    int hw = (oy + ty) * Wd + (ox + tx);
    g_ew[b * HW + hw] = sig * g_cons[b * HW + hw];
}

// ---------------- K5/K6: 3x3 conv 64->64 via bf16 mma.sync implicit GEMM -------
#define XS_BYTES 23040
#define WS_BYTES 73728
#define CONV_SMEM (XS_BYTES + WS_BYTES)

extern "C" __global__ void __launch_bounds__(256, 2)
k_conv_mma(int mode, int wqoff, const float* __restrict__ bias,
           const float* __restrict__ xres, const float* __restrict__ alphap,
           float* __restrict__ out) {
    extern __shared__ char dsm[];
    __nv_bfloat16* Xs = (__nv_bfloat16*)dsm;
    u64* Ws = (u64*)(dsm + XS_BYTES);
    __shared__ float sbias[64];

    int tid = threadIdx.x;
    int lane = tid & 31, w = tid >> 5;
    int bcol = blockIdx.x * 16, brow = blockIdx.y * 8;
    int b = blockIdx.z;

    {
        const float4* src = (const float4*)(g_wq + wqoff);
        float4* dst = (float4*)Ws;
        for (int i = tid; i < WS_BYTES / 16; i += 256) dst[i] = src[i];
    }
    if (tid < 64) sbias[tid] = bias[tid];

    const __nv_bfloat16* xb =
        (mode == 0 ? g_xb : g_eeb) + (size_t)b * HW * 64;
    for (int i = tid; i < 180 * 8; i += 256) {
        int p = i >> 3, seg = i & 7;
        int r = p / 18, c = p - r * 18;
        int gh = brow - 1 + r, gc = bcol - 1 + c;
        uint4 v = make_uint4(0, 0, 0, 0);
        if ((unsigned)gh < (unsigned)H && (unsigned)gc < (unsigned)Wd)
            v = *(const uint4*)((const char*)xb +
                                ((size_t)(gh * Wd + gc)) * 128 + seg * 16);
        *(uint4*)((char*)Xs + p * 128 + ((seg * 16) ^ ((p & 7) << 4))) = v;
    }
    __syncthreads();

    float acc[8][4];
#pragma unroll
    for (int nt = 0; nt < 8; nt++)
#pragma unroll
        for (int k = 0; k < 4; k++) acc[nt][k] = 0.f;

    u32 xs_base = s2u(Xs);
    int m = lane & 15;
    int kb = (lane >> 4) << 4;
    int nq = (lane >> 2) * 4 + (lane & 3);

#pragma unroll
    for (int ky = 0; ky < 3; ky++) {
#pragma unroll
        for (int kx = 0; kx < 3; kx++) {
            int p = (w + ky) * 18 + kx + m;
            u32 arow = xs_base + p * 128;
            u32 swz = (u32)((p & 7) << 4);
            const u64* wd = Ws + ((ky * 3 + kx) * 4) * 256 + nq;
#pragma unroll
            for (int kc = 0; kc < 4; kc++) {
                u32 a0, a1, a2, a3;
                u32 addr = arow + ((u32)(kc * 32 + kb) ^ swz);
                asm volatile(
                    "ldmatrix.sync.aligned.m8n8.x4.shared.b16 "
                    "{%0,%1,%2,%3}, [%4];"
                    : "=r"(a0), "=r"(a1), "=r"(a2), "=r"(a3)
                    : "r"(addr));
                const u64* wk = wd + kc * 256;
#pragma unroll
                for (int nt = 0; nt < 8; nt++) {
                    u64 bv = wk[nt * 32];
                    u32 b0 = (u32)bv, b1 = (u32)(bv >> 32);
                    asm volatile(
                        "mma.sync.aligned.m16n8k16.row.col.f32.bf16.bf16.f32 "
                        "{%0,%1,%2,%3}, {%4,%5,%6,%7}, {%8,%9}, {%0,%1,%2,%3};"
                        : "+f"(acc[nt][0]), "+f"(acc[nt][1]),
                          "+f"(acc[nt][2]), "+f"(acc[nt][3])
                        : "r"(a0), "r"(a1), "r"(a2), "r"(a3),
                          "r"(b0), "r"(b1));
                }
            }
        }
    }

    int g = lane >> 2, t = lane & 3;
    if (mode == 0) {
        int h = brow + w;
        size_t px0 = (size_t)b * HW + h * Wd + bcol + g;
#pragma unroll
        for (int nt = 0; nt < 8; nt++) {
            int oc = nt * 8 + 2 * t;
            float b0f = sbias[oc], b1f = sbias[oc + 1];
            __nv_bfloat162 p01 = __floats2bfloat162_rn(
                fmaxf(acc[nt][0] + b0f, 0.f), fmaxf(acc[nt][1] + b1f, 0.f));
            __nv_bfloat162 p23 = __floats2bfloat162_rn(
                fmaxf(acc[nt][2] + b0f, 0.f), fmaxf(acc[nt][3] + b1f, 0.f));
            *(u32*)&g_eeb[px0 * 64 + oc] = *(u32*)&p01;
            *(u32*)&g_eeb[(px0 + 8) * 64 + oc] = *(u32*)&p23;
        }
    } else {
        float* sep = (float*)dsm;
        __syncthreads();
        int pl0 = w * 16 + g;
#pragma unroll
        for (int nt = 0; nt < 8; nt++) {
            int oc = nt * 8 + 2 * t;
            sep[oc * 132 + pl0]           = acc[nt][0] + sbias[oc];
            sep[(oc + 1) * 132 + pl0]     = acc[nt][1] + sbias[oc + 1];
            sep[oc * 132 + pl0 + 8]       = acc[nt][2] + sbias[oc];
            sep[(oc + 1) * 132 + pl0 + 8] = acc[nt][3] + sbias[oc + 1];
        }
        __syncthreads();
        float alpha = __ldg(alphap);
        for (int i = tid; i < 8192; i += 256) {
            int oc = i >> 7, pxl = i & 127;
            int h = brow + (pxl >> 4), col = bcol + (pxl & 15);
            int gpx = h * Wd + col;
            float v = sep[oc * 132 + pxl];
            float e = g_ew[b * HW + gpx];
            size_t oi = ((size_t)b * C + oc) * HW + gpx;
            out[oi] = xres[oi] + alpha * e * v;
        }
    }
}

// ---------------- launch ----------------
extern "C" void kernel_launch(void* const* d_in, const int* in_sizes, int n_in,
                              void* d_out, int out_size) {
    const float* x     = (const float*)d_in[0];
    const float* ga_w1 = (const float*)d_in[3];
    const float* ga_b1 = (const float*)d_in[4];
    const float* ga_w2 = (const float*)d_in[5];
    const float* ga_b2 = (const float*)d_in[6];
    const float* cd_w1 = (const float*)d_in[7];
    const float* cd_b1 = (const float*)d_in[8];
    const float* cd_w2 = (const float*)d_in[9];
    const float* cd_b2 = (const float*)d_in[10];
    const float* ec_w1 = (const float*)d_in[11];
    const float* ec_b1 = (const float*)d_in[12];
    const float* ec_w2 = (const float*)d_in[13];
    const float* ec_b2 = (const float*)d_in[14];
    const float* alpha = (const float*)d_in[15];
    float* out = (float*)d_out;

    cudaFuncSetAttribute(k_conv_mma,
                         cudaFuncAttributeMaxDynamicSharedMemorySize, CONV_SMEM);
    cudaFuncSetAttribute(k2_mma,
                         cudaFuncAttributeMaxDynamicSharedMemorySize, K2_SMEM);

    k_pre<<<2688, 256>>>(x, ec_w1, ec_w2, ga_w1, ga_w2);
    k2_mma<<<B * HW / 64, 128, K2_SMEM>>>(ga_b1, ga_b2);
    k3_cons<<<dim3(4, 4, B * 16), dim3(32, 8)>>>();
    k4_cd<<<dim3(8, 16, B), dim3(16, 8)>>>(cd_w1, cd_b1, cd_w2, cd_b2);
    k_conv_mma<<<dim3(8, 16, B), 256, CONV_SMEM>>>(0, 0, ec_b1, x, alpha, out);
    k_conv_mma<<<dim3(8, 16, B), 256, CONV_SMEM>>>(1, 9216, ec_b2, x, alpha, out);
}

// round 7
// speedup vs baseline: 8.0372x; 1.1790x over previous
#include <cuda_runtime.h>
#include <cuda_bf16.h>
#include <math.h>

#define B 2
#define C 64
#define C4 16
#define H 128
#define Wd 128
#define HW (H * Wd)
#define EPSF 1e-6f

typedef unsigned long long u64;
typedef unsigned int u32;

// ---------------- scratch (device globals; no allocation allowed) ----------------
__device__ float g_gx[B * C * HW];
__device__ float g_gy[B * C * HW];
__device__ float g_cons[B * HW];
__device__ float g_ew[B * HW];
__device__ __align__(16) __nv_bfloat16 g_ga2b[B * HW * C4];  // ga2, px-major bf16
__device__ __align__(16) __nv_bfloat16 g_xb[B * HW * C];     // x, NHWC bf16
__device__ __align__(16) __nv_bfloat16 g_eeb[B * HW * C];    // relu(conv1), NHWC bf16
__device__ __align__(16) u64 g_wq[2 * 9 * 4 * 64 * 4];       // conv B fragments
__device__ __align__(16) u64 g_wga1[2048];                   // ga layer1 B fragments
__device__ __align__(16) u64 g_wga2[256];                    // ga layer2 B fragments
__device__ __align__(16) u64 g_wcd[576];                     // cd conv B fragments

__device__ __forceinline__ u32 s2u(const void* p) {
    return (u32)__cvta_generic_to_shared(p);
}

// ---------------- fast math (approx, errors << 1e-3 tolerance) ----------------
__device__ __forceinline__ float fsqrt_ap(float v) {
    float r; asm("sqrt.approx.f32 %0, %1;" : "=f"(r) : "f"(v)); return r;
}
__device__ __forceinline__ float ftanh_ap(float v) {
    float r; asm("tanh.approx.f32 %0, %1;" : "=f"(r) : "f"(v)); return r;
}
__device__ __forceinline__ float frcp_ap(float v) {
    float r; asm("rcp.approx.f32 %0, %1;" : "=f"(r) : "f"(v)); return r;
}
__device__ __forceinline__ float fatan2_ap(float y, float x) {
    float ax = fabsf(x), ay = fabsf(y);
    float mx = fmaxf(ax, ay), mn = fminf(ax, ay);
    float z = __fdividef(mn, fmaxf(mx, 1e-30f));
    float s = z * z;
    float p = fmaf(s, -0.0117212f, 0.0526533f);
    p = fmaf(s, p, -0.1164329f);
    p = fmaf(s, p, 0.1935435f);
    p = fmaf(s, p, -0.3326235f);
    p = fmaf(s, p, 0.9999773f);
    float r = p * z;
    if (ay > ax) r = 1.57079632679f - r;
    if (x < 0.f) r = 3.14159265359f - r;
    return copysignf(r, y);
}

// ---------------- K_PRE: weight packs + g_cons zero + x->NHWC bf16 + sobel ----
// grid.x: [0,128) wprep, [128,640) xprep, [640,2688) sobel 32x32 tiles
__global__ __launch_bounds__(256) void k_pre(const float* __restrict__ x,
                                             const float* __restrict__ w1,
                                             const float* __restrict__ w2,
                                             const float* __restrict__ gw1,
                                             const float* __restrict__ gw2,
                                             const float* __restrict__ cw1) {
    __shared__ __align__(16) char sm[16640];
    int bx = blockIdx.x, tid = threadIdx.x;

    if (bx < 128) {
        int i = bx * 256 + tid;
        g_cons[i] = 0.f;
        if (i < 2 * 9216) {      // conv weights
            int cv = i / 9216;
            int r = i % 9216;
            int dlt = r / 1024;
            int r2 = r % 1024;
            int kc = r2 / 256;
            int r3 = r2 % 256;
            int n = r3 / 4, q = r3 % 4;
            const float* w = cv ? w2 : w1;
            int ic0 = kc * 16 + 2 * q;
            __nv_bfloat162 lo = __floats2bfloat162_rn(
                w[(n * 64 + ic0) * 9 + dlt], w[(n * 64 + ic0 + 1) * 9 + dlt]);
            __nv_bfloat162 hi = __floats2bfloat162_rn(
                w[(n * 64 + ic0 + 8) * 9 + dlt], w[(n * 64 + ic0 + 9) * 9 + dlt]);
            g_wq[i] = (u64)(*(u32*)&lo) | ((u64)(*(u32*)&hi) << 32);
        }
        if (i < 2048) {          // ga_w1 fragments
            int kstep = i >> 8;
            int nt = (i >> 5) & 7;
            int l = i & 31;
            int n_oc = nt * 8 + (l >> 2);
            int k0 = kstep * 16 + (l & 3) * 2;
            __nv_bfloat162 lo = __floats2bfloat162_rn(
                gw1[n_oc * 128 + k0], gw1[n_oc * 128 + k0 + 1]);
            __nv_bfloat162 hi = __floats2bfloat162_rn(
                gw1[n_oc * 128 + k0 + 8], gw1[n_oc * 128 + k0 + 9]);
            g_wga1[i] = (u64)(*(u32*)&lo) | ((u64)(*(u32*)&hi) << 32);
        }
        if (i < 256) {           // ga_w2 fragments
            int kstep = i >> 6;
            int nt = (i >> 5) & 1;
            int l = i & 31;
            int n_oc = nt * 8 + (l >> 2);
            int k0 = kstep * 16 + (l & 3) * 2;
            __nv_bfloat162 lo = __floats2bfloat162_rn(
                gw2[n_oc * 64 + k0], gw2[n_oc * 64 + k0 + 1]);
            __nv_bfloat162 hi = __floats2bfloat162_rn(
                gw2[n_oc * 64 + k0 + 8], gw2[n_oc * 64 + k0 + 9]);
            g_wga2[i] = (u64)(*(u32*)&lo) | ((u64)(*(u32*)&hi) << 32);
        }
        if (i < 576) {           // cd conv fragments: [tap][nt][lane]
            int tap = i >> 6;
            int nt = (i >> 5) & 1;
            int l = i & 31;
            int n_oc = nt * 8 + (l >> 2);
            int ic0 = (l & 3) * 2;
            __nv_bfloat162 lo = __floats2bfloat162_rn(
                cw1[(n_oc * 16 + ic0) * 9 + tap],
                cw1[(n_oc * 16 + ic0 + 1) * 9 + tap]);
            __nv_bfloat162 hi = __floats2bfloat162_rn(
                cw1[(n_oc * 16 + ic0 + 8) * 9 + tap],
                cw1[(n_oc * 16 + ic0 + 9) * 9 + tap]);
            g_wcd[i] = (u64)(*(u32*)&lo) | ((u64)(*(u32*)&hi) << 32);
        }
    } else if (bx < 640) {
        // x (NCHW fp32) -> g_xb (NHWC bf16), 64 px per block
        int bb = bx - 128;
        int b = bb >> 8;
        int px0 = (bb & 255) * 64;
        float* s = (float*)sm;   // [64 px][65]
        const float* xb = x + (size_t)b * C * HW;
        for (int i = tid; i < 4096; i += 256) {
            int ic = i >> 6, p = i & 63;
            s[p * 65 + ic] = xb[(size_t)ic * HW + px0 + p];
        }
        __syncthreads();
#pragma unroll
        for (int it = 0; it < 2; it++) {
            int idx = tid + it * 256;
            int p = idx >> 3, seg = idx & 7;
            const float* sp = &s[p * 65 + seg * 8];
            u32 u[4];
#pragma unroll
            for (int k = 0; k < 4; k++) {
                __nv_bfloat162 h2 = __floats2bfloat162_rn(sp[2 * k], sp[2 * k + 1]);
                u[k] = *(u32*)&h2;
            }
            *(uint4*)&g_xb[((size_t)b * HW + px0 + p) * 64 + seg * 8] =
                make_uint4(u[0], u[1], u[2], u[3]);
        }
    } else {
        // depthwise sobel, 32x32 tile per block
        int z = bx - 640;
        int plane = z >> 4;
        int oy = ((z >> 2) & 3) * 32, ox = (z & 3) * 32;
        float* sx = (float*)sm;  // [34*34]
        const float* xp = x + (size_t)plane * HW;
        for (int i = tid; i < 1156; i += 256) {
            int r = i / 34, c = i - r * 34;
            int gh = oy + r - 1, gw = ox + c - 1;
            float v = 0.f;
            if ((unsigned)gh < (unsigned)H && (unsigned)gw < (unsigned)Wd)
                v = xp[gh * Wd + gw];
            sx[r * 34 + c] = v;
        }
        __syncthreads();
#pragma unroll
        for (int k = 0; k < 4; k++) {
            int px = tid + k * 256;
            int row = px >> 5, col = px & 31;
            const float* s0 = sx + row * 34 + col;
            float a00 = s0[0],  a01 = s0[1],  a02 = s0[2];
            float a10 = s0[34],               a12 = s0[36];
            float a20 = s0[68], a21 = s0[69], a22 = s0[70];
            float gx = (a02 - a00) + 2.f * (a12 - a10) + (a22 - a20);
            float gy = (a20 - a00) + 2.f * (a21 - a01) + (a22 - a02);
            int idx = plane * HW + (oy + row) * Wd + ox + col;
            g_gx[idx] = gx;
            g_gy[idx] = gy;
        }
    }
}

// ---------------- K2: fused 1x1 chain via bf16 mma (128 -> 64 relu -> 16 relu) ----
// 4 warps, 64 px per block, 512 blocks. Output: g_ga2b px-major bf16.
#define K2_SMEM 43328
extern "C" __global__ void __launch_bounds__(128)
k2_mma(const float* __restrict__ b1, const float* __restrict__ b2) {
    extern __shared__ char smb[];
    __nv_bfloat16* sIn = (__nv_bfloat16*)smb;            // 2 halves x 64px x 128B
    __nv_bfloat16* sHid = (__nv_bfloat16*)(smb + 16384); // 64px x 128B
    u64* sW1 = (u64*)(smb + 24576);                      // 2048 u64
    u64* sW2 = (u64*)(smb + 40960);                      // 256 u64
    float* sb1 = (float*)(smb + 43008);                  // 64
    float* sb2 = (float*)(smb + 43264);                  // 16

    int tid = threadIdx.x, lane = tid & 31, w = tid >> 5;
    int b = blockIdx.x >> 8;
    int px0 = (blockIdx.x & 255) * 64;

    {
        const float4* s1 = (const float4*)g_wga1;
        float4* d1 = (float4*)sW1;
#pragma unroll
        for (int i = tid; i < 1024; i += 128) d1[i] = s1[i];
        ((float4*)sW2)[tid] = ((const float4*)g_wga2)[tid];
        if (tid < 64) sb1[tid] = b1[tid];
        if (tid < 16) sb2[tid] = b2[tid];
    }
    const float* gxp = g_gx + (size_t)b * C * HW + px0;
    const float* gyp = g_gy + (size_t)b * C * HW + px0;
    for (int i = tid; i < 4096; i += 128) {
        int cp = i >> 6, px = i & 63;
        const float* pl = (cp < 32) ? (gxp + (size_t)(cp * 2) * HW)
                                    : (gyp + (size_t)((cp - 32) * 2) * HW);
        __nv_bfloat162 hv = __floats2bfloat162_rn(pl[px], pl[HW + px]);
        int half = cp >> 5, c4 = (cp & 31) * 4;
        *(u32*)((char*)sIn + half * 8192 + px * 128 +
                ((u32)c4 ^ ((u32)(px & 7) << 4))) = *(u32*)&hv;
    }
    __syncthreads();

    int m = lane & 15, kb = (lane >> 4) << 4;
    int p = w * 16 + m;
    u32 swz = (u32)((p & 7) << 4);
    u32 arow = s2u(sIn) + p * 128;

    float acc[8][4];
#pragma unroll
    for (int nt = 0; nt < 8; nt++)
#pragma unroll
        for (int k = 0; k < 4; k++) acc[nt][k] = 0.f;

#pragma unroll
    for (int kc = 0; kc < 8; kc++) {
        u32 a0, a1, a2, a3;
        u32 addr = arow + (kc >> 2) * 8192 + (((u32)((kc & 3) * 32 + kb)) ^ swz);
        asm volatile(
            "ldmatrix.sync.aligned.m8n8.x4.shared.b16 {%0,%1,%2,%3}, [%4];"
            : "=r"(a0), "=r"(a1), "=r"(a2), "=r"(a3) : "r"(addr));
        const u64* wk = sW1 + (size_t)kc * 256 + lane;
#pragma unroll
        for (int nt = 0; nt < 8; nt++) {
            u64 bv = wk[nt * 32];
            u32 bf0 = (u32)bv, bf1 = (u32)(bv >> 32);
            asm volatile(
                "mma.sync.aligned.m16n8k16.row.col.f32.bf16.bf16.f32 "
                "{%0,%1,%2,%3}, {%4,%5,%6,%7}, {%8,%9}, {%0,%1,%2,%3};"
                : "+f"(acc[nt][0]), "+f"(acc[nt][1]),
                  "+f"(acc[nt][2]), "+f"(acc[nt][3])
                : "r"(a0), "r"(a1), "r"(a2), "r"(a3), "r"(bf0), "r"(bf1));
        }
    }

    int rr = lane >> 2, cc0 = (lane & 3) * 2;
    int pr0 = w * 16 + rr, pr1 = pr0 + 8;
#pragma unroll
    for (int nt = 0; nt < 8; nt++) {
        int oc = nt * 8 + cc0;
        float bb0 = sb1[oc], bb1 = sb1[oc + 1];
        __nv_bfloat162 v01 = __floats2bfloat162_rn(
            fmaxf(acc[nt][0] + bb0, 0.f), fmaxf(acc[nt][1] + bb1, 0.f));
        __nv_bfloat162 v23 = __floats2bfloat162_rn(
            fmaxf(acc[nt][2] + bb0, 0.f), fmaxf(acc[nt][3] + bb1, 0.f));
        *(u32*)((char*)sHid + pr0 * 128 +
                ((u32)(oc * 2) ^ ((u32)(pr0 & 7) << 4))) = *(u32*)&v01;
        *(u32*)((char*)sHid + pr1 * 128 +
                ((u32)(oc * 2) ^ ((u32)(pr1 & 7) << 4))) = *(u32*)&v23;
    }
    __syncwarp();

    float a2c[2][4];
#pragma unroll
    for (int nt = 0; nt < 2; nt++)
#pragma unroll
        for (int k = 0; k < 4; k++) a2c[nt][k] = 0.f;

    u32 hrow = s2u(sHid) + p * 128;
#pragma unroll
    for (int kc = 0; kc < 4; kc++) {
        u32 a0, a1, a2, a3;
        u32 addr = hrow + (((u32)(kc * 32 + kb)) ^ swz);
        asm volatile(
            "ldmatrix.sync.aligned.m8n8.x4.shared.b16 {%0,%1,%2,%3}, [%4];"
            : "=r"(a0), "=r"(a1), "=r"(a2), "=r"(a3) : "r"(addr));
        const u64* wk = sW2 + (size_t)kc * 64 + lane;
#pragma unroll
        for (int nt = 0; nt < 2; nt++) {
            u64 bv = wk[nt * 32];
            u32 bf0 = (u32)bv, bf1 = (u32)(bv >> 32);
            asm volatile(
                "mma.sync.aligned.m16n8k16.row.col.f32.bf16.bf16.f32 "
                "{%0,%1,%2,%3}, {%4,%5,%6,%7}, {%8,%9}, {%0,%1,%2,%3};"
                : "+f"(a2c[nt][0]), "+f"(a2c[nt][1]),
                  "+f"(a2c[nt][2]), "+f"(a2c[nt][3])
                : "r"(a0), "r"(a1), "r"(a2), "r"(a3), "r"(bf0), "r"(bf1));
        }
    }

    // bias + relu -> g_ga2b px-major bf16 (16 ch per px)
    size_t pxg0 = (size_t)b * HW + px0 + w * 16 + rr;
#pragma unroll
    for (int nt = 0; nt < 2; nt++) {
        int oc = nt * 8 + cc0;
        float bb0 = sb2[oc], bb1 = sb2[oc + 1];
        __nv_bfloat162 v01 = __floats2bfloat162_rn(
            fmaxf(a2c[nt][0] + bb0, 0.f), fmaxf(a2c[nt][1] + bb1, 0.f));
        __nv_bfloat162 v23 = __floats2bfloat162_rn(
            fmaxf(a2c[nt][2] + bb0, 0.f), fmaxf(a2c[nt][3] + bb1, 0.f));
        *(u32*)&g_ga2b[pxg0 * 16 + oc] = *(u32*)&v01;
        *(u32*)&g_ga2b[(pxg0 + 8) * 16 + oc] = *(u32*)&v23;
    }
}

// ---------------- K3: windowed weighted direction stats (32x32, fast math) -----
__global__ __launch_bounds__(256) void k3_cons() {
    __shared__ float sm0[36][36];
    __shared__ float sm1[36][36];
    __shared__ float sm2[36][36];
    __shared__ float h0[36][32];
    __shared__ float h1[36][32];
    __shared__ float h2[36][32];
    int b = blockIdx.z >> 4;
    int cg = blockIdx.z & 15;
    int oy = blockIdx.y * 32, ox = blockIdx.x * 32;
    int tx = threadIdx.x, ty = threadIdx.y;       // (32, 8)
    int tid = ty * 32 + tx;

    float cons[4] = {0.f, 0.f, 0.f, 0.f};
    for (int cc = 0; cc < 4; cc++) {
        int c = cg * 4 + cc;
        int base = (b * C + c) * HW;
        __syncthreads();
        for (int i = tid; i < 1296; i += 256) {
            int r = i / 36, k = i % 36;
            int gh = oy + r - 2, gw = ox + k - 2;
            float m0 = 0.f, m1 = 0.f, m2 = 0.f;
            if ((unsigned)gh < (unsigned)H && (unsigned)gw < (unsigned)Wd) {
                int gi = base + gh * Wd + gw;
                float gx = g_gx[gi], gy = g_gy[gi];
                float mag = fsqrt_ap(gx * gx + gy * gy + EPSF);
                float dir = fatan2_ap(gy, gx);
                m0 = mag;
                m1 = mag * dir;
                m2 = m1 * dir;
            }
            sm0[r][k] = m0;
            sm1[r][k] = m1;
            sm2[r][k] = m2;
        }
        __syncthreads();
        for (int i = tid; i < 1152; i += 256) {
            int r = i >> 5, k = i & 31;
            float a0 = 0.f, a1 = 0.f, a2 = 0.f;
#pragma unroll
            for (int d = 0; d < 5; d++) {
                a0 += sm0[r][k + d];
                a1 += sm1[r][k + d];
                a2 += sm2[r][k + d];
            }
            h0[r][k] = a0;
            h1[r][k] = a1;
            h2[r][k] = a2;
        }
        __syncthreads();
#pragma unroll
        for (int j = 0; j < 4; j++) {
            int row = ty + 8 * j;
            float s0 = 0.f, s1 = 0.f, s2 = 0.f;
#pragma unroll
            for (int d = 0; d < 5; d++) {
                s0 += h0[row + d][tx];
                s1 += h1[row + d][tx];
                s2 += h2[row + d][tx];
            }
            float inv = frcp_ap(s0 + EPSF);
            float wmean = s1 * inv;
            float wvar = (s2 - 2.f * wmean * s1 + wmean * wmean * s0) * inv;
            wvar = fmaxf(wvar, 0.f);
            cons[j] += 1.f - ftanh_ap(fsqrt_ap(wvar));
        }
    }
#pragma unroll
    for (int j = 0; j < 4; j++)
        atomicAdd(&g_cons[b * HW + (oy + ty + 8 * j) * Wd + (ox + tx)],
                  cons[j] * (1.f / (float)C));
}

// ---------------- K4: cd branch via bf16 mma (3x3 16->16 relu, 1x1->1, sigmoid) ----
// 8 warps; warp w owns px row (brow+w), 16 cols. K = 9 taps x 16 ic.
__global__ __launch_bounds__(256) void k4_mma(const float* __restrict__ cb1,
                                              const float* __restrict__ cw2,
                                              const float* __restrict__ cb2) {
    __shared__ __align__(16) char sga[180 * 48];   // halo px rows, 48B stride
    __shared__ __align__(16) u64 sW[576];
    __shared__ float b1s[16], w2s[16];
    __shared__ float b2s_;

    int tid = threadIdx.x, lane = tid & 31, w = tid >> 5;
    int bi = blockIdx.x;
    int b = bi >> 7;
    int t8 = bi & 127;
    int brow = (t8 >> 3) * 8, bcol = (t8 & 7) * 16;

    for (int i = tid; i < 576; i += 256) sW[i] = g_wcd[i];
    if (tid < 16) { b1s[tid] = cb1[tid]; w2s[tid] = cw2[tid]; }
    if (tid == 0) b2s_ = cb2[0];

    // stage halo: 10x18 px, 32B of channels each, 48B row stride (conflict-free)
    const __nv_bfloat16* gb = g_ga2b + (size_t)b * HW * 16;
    for (int i = tid; i < 360; i += 256) {
        int p = i >> 1, hf = i & 1;
        int r = p / 18, c = p - r * 18;
        int gh = brow - 1 + r, gc = bcol - 1 + c;
        uint4 v = make_uint4(0, 0, 0, 0);
        if ((unsigned)gh < (unsigned)H && (unsigned)gc < (unsigned)Wd)
            v = *(const uint4*)&gb[(size_t)(gh * Wd + gc) * 16 + hf * 8];
        *(uint4*)(sga + p * 48 + hf * 16) = v;
    }
    __syncthreads();

    float acc[2][4];
#pragma unroll
    for (int nt = 0; nt < 2; nt++)
#pragma unroll
        for (int k = 0; k < 4; k++) acc[nt][k] = 0.f;

    int m = lane & 15, kb = (lane >> 4) << 4;
    u32 base = s2u(sga);
#pragma unroll
    for (int ky = 0; ky < 3; ky++) {
#pragma unroll
        for (int kx = 0; kx < 3; kx++) {
            int tap = ky * 3 + kx;
            u32 addr = base + (u32)(((w + ky) * 18 + kx + m) * 48 + kb);
            u32 a0, a1, a2, a3;
            asm volatile(
                "ldmatrix.sync.aligned.m8n8.x4.shared.b16 {%0,%1,%2,%3}, [%4];"
                : "=r"(a0), "=r"(a1), "=r"(a2), "=r"(a3) : "r"(addr));
            const u64* wk = sW + tap * 64 + lane;
#pragma unroll
            for (int nt = 0; nt < 2; nt++) {
                u64 bv = wk[nt * 32];
                u32 bf0 = (u32)bv, bf1 = (u32)(bv >> 32);
                asm volatile(
                    "mma.sync.aligned.m16n8k16.row.col.f32.bf16.bf16.f32 "
                    "{%0,%1,%2,%3}, {%4,%5,%6,%7}, {%8,%9}, {%0,%1,%2,%3};"
                    : "+f"(acc[nt][0]), "+f"(acc[nt][1]),
                      "+f"(acc[nt][2]), "+f"(acc[nt][3])
                    : "r"(a0), "r"(a1), "r"(a2), "r"(a3), "r"(bf0), "r"(bf1));
            }
        }
    }

    // epilogue: relu + 1x1 (16->1) via quad reduce, sigmoid, * cons
    int r0 = lane >> 2, t = lane & 3;
    float p0 = 0.f, p1 = 0.f;
#pragma unroll
    for (int nt = 0; nt < 2; nt++) {
        int oc = nt * 8 + 2 * t;
        float w0 = w2s[oc], w1v = w2s[oc + 1];
        float bb0 = b1s[oc], bb1 = b1s[oc + 1];
        p0 += w0 * fmaxf(acc[nt][0] + bb0, 0.f) + w1v * fmaxf(acc[nt][1] + bb1, 0.f);
        p1 += w0 * fmaxf(acc[nt][2] + bb0, 0.f) + w1v * fmaxf(acc[nt][3] + bb1, 0.f);
    }
    p0 += __shfl_xor_sync(0xffffffffu, p0, 1);
    p0 += __shfl_xor_sync(0xffffffffu, p0, 2);
    p1 += __shfl_xor_sync(0xffffffffu, p1, 1);
    p1 += __shfl_xor_sync(0xffffffffu, p1, 2);

    if (t == 0) {
        int gpx = (brow + w) * Wd + bcol + r0;
        float s0 = p0 + b2s_, s1 = p1 + b2s_;
        g_ew[b * HW + gpx] =
            frcp_ap(1.f + __expf(-s0)) * g_cons[b * HW + gpx];
        g_ew[b * HW + gpx + 8] =
            frcp_ap(1.f + __expf(-s1)) * g_cons[b * HW + gpx + 8];
    }
}

// ---------------- K5/K6: 3x3 conv 64->64 via bf16 mma.sync implicit GEMM -------
#define XS_BYTES 23040
#define WS_BYTES 73728
#define CONV_SMEM (XS_BYTES + WS_BYTES)

extern "C" __global__ void __launch_bounds__(256, 2)
k_conv_mma(int mode, int wqoff, const float* __restrict__ bias,
           const float* __restrict__ xres, const float* __restrict__ alphap,
           float* __restrict__ out) {
    extern __shared__ char dsm[];
    __nv_bfloat16* Xs = (__nv_bfloat16*)dsm;
    u64* Ws = (u64*)(dsm + XS_BYTES);
    __shared__ float sbias[64];

    int tid = threadIdx.x;
    int lane = tid & 31, w = tid >> 5;
    int bcol = blockIdx.x * 16, brow = blockIdx.y * 8;
    int b = blockIdx.z;

    {
        const float4* src = (const float4*)(g_wq + wqoff);
        float4* dst = (float4*)Ws;
        for (int i = tid; i < WS_BYTES / 16; i += 256) dst[i] = src[i];
    }
    if (tid < 64) sbias[tid] = bias[tid];

    const __nv_bfloat16* xb =
        (mode == 0 ? g_xb : g_eeb) + (size_t)b * HW * 64;
    for (int i = tid; i < 180 * 8; i += 256) {
        int p = i >> 3, seg = i & 7;
        int r = p / 18, c = p - r * 18;
        int gh = brow - 1 + r, gc = bcol - 1 + c;
        uint4 v = make_uint4(0, 0, 0, 0);
        if ((unsigned)gh < (unsigned)H && (unsigned)gc < (unsigned)Wd)
            v = *(const uint4*)((const char*)xb +
                                ((size_t)(gh * Wd + gc)) * 128 + seg * 16);
        *(uint4*)((char*)Xs + p * 128 + ((seg * 16) ^ ((p & 7) << 4))) = v;
    }
    __syncthreads();

    float acc[8][4];
#pragma unroll
    for (int nt = 0; nt < 8; nt++)
#pragma unroll
        for (int k = 0; k < 4; k++) acc[nt][k] = 0.f;

    u32 xs_base = s2u(Xs);
    int m = lane & 15;
    int kb = (lane >> 4) << 4;
    int nq = (lane >> 2) * 4 + (lane & 3);

#pragma unroll
    for (int ky = 0; ky < 3; ky++) {
#pragma unroll
        for (int kx = 0; kx < 3; kx++) {
            int p = (w + ky) * 18 + kx + m;
            u32 arow = xs_base + p * 128;
            u32 swz = (u32)((p & 7) << 4);
            const u64* wd = Ws + ((ky * 3 + kx) * 4) * 256 + nq;
#pragma unroll
            for (int kc = 0; kc < 4; kc++) {
                u32 a0, a1, a2, a3;
                u32 addr = arow + ((u32)(kc * 32 + kb) ^ swz);
                asm volatile(
                    "ldmatrix.sync.aligned.m8n8.x4.shared.b16 "
                    "{%0,%1,%2,%3}, [%4];"
                    : "=r"(a0), "=r"(a1), "=r"(a2), "=r"(a3)
                    : "r"(addr));
                const u64* wk = wd + kc * 256;
#pragma unroll
                for (int nt = 0; nt < 8; nt++) {
                    u64 bv = wk[nt * 32];
                    u32 b0 = (u32)bv, b1 = (u32)(bv >> 32);
                    asm volatile(
                        "mma.sync.aligned.m16n8k16.row.col.f32.bf16.bf16.f32 "
                        "{%0,%1,%2,%3}, {%4,%5,%6,%7}, {%8,%9}, {%0,%1,%2,%3};"
                        : "+f"(acc[nt][0]), "+f"(acc[nt][1]),
                          "+f"(acc[nt][2]), "+f"(acc[nt][3])
                        : "r"(a0), "r"(a1), "r"(a2), "r"(a3),
                          "r"(b0), "r"(b1));
                }
            }
        }
    }

    int g = lane >> 2, t = lane & 3;
    if (mode == 0) {
        int h = brow + w;
        size_t px0 = (size_t)b * HW + h * Wd + bcol + g;
#pragma unroll
        for (int nt = 0; nt < 8; nt++) {
            int oc = nt * 8 + 2 * t;
            float b0f = sbias[oc], b1f = sbias[oc + 1];
            __nv_bfloat162 p01 = __floats2bfloat162_rn(
                fmaxf(acc[nt][0] + b0f, 0.f), fmaxf(acc[nt][1] + b1f, 0.f));
            __nv_bfloat162 p23 = __floats2bfloat162_rn(
                fmaxf(acc[nt][2] + b0f, 0.f), fmaxf(acc[nt][3] + b1f, 0.f));
            *(u32*)&g_eeb[px0 * 64 + oc] = *(u32*)&p01;
            *(u32*)&g_eeb[(px0 + 8) * 64 + oc] = *(u32*)&p23;
        }
    } else {
        float* sep = (float*)dsm;
        __syncthreads();
        int pl0 = w * 16 + g;
#pragma unroll
        for (int nt = 0; nt < 8; nt++) {
            int oc = nt * 8 + 2 * t;
            sep[oc * 132 + pl0]           = acc[nt][0] + sbias[oc];
            sep[(oc + 1) * 132 + pl0]     = acc[nt][1] + sbias[oc + 1];
            sep[oc * 132 + pl0 + 8]       = acc[nt][2] + sbias[oc];
            sep[(oc + 1) * 132 + pl0 + 8] = acc[nt][3] + sbias[oc + 1];
        }
        __syncthreads();
        float alpha = __ldg(alphap);
        for (int i = tid; i < 8192; i += 256) {
            int oc = i >> 7, pxl = i & 127;
            int h = brow + (pxl >> 4), col = bcol + (pxl & 15);
            int gpx = h * Wd + col;
            float v = sep[oc * 132 + pxl];
            float e = g_ew[b * HW + gpx];
            size_t oi = ((size_t)b * C + oc) * HW + gpx;
            out[oi] = xres[oi] + alpha * e * v;
        }
    }
}

// ---------------- launch ----------------
extern "C" void kernel_launch(void* const* d_in, const int* in_sizes, int n_in,
                              void* d_out, int out_size) {
    const float* x     = (const float*)d_in[0];
    const float* ga_w1 = (const float*)d_in[3];
    const float* ga_b1 = (const float*)d_in[4];
    const float* ga_w2 = (const float*)d_in[5];
    const float* ga_b2 = (const float*)d_in[6];
    const float* cd_w1 = (const float*)d_in[7];
    const float* cd_b1 = (const float*)d_in[8];
    const float* cd_w2 = (const float*)d_in[9];
    const float* cd_b2 = (const float*)d_in[10];
    const float* ec_w1 = (const float*)d_in[11];
    const float* ec_b1 = (const float*)d_in[12];
    const float* ec_w2 = (const float*)d_in[13];
    const float* ec_b2 = (const float*)d_in[14];
    const float* alpha = (const float*)d_in[15];
    float* out = (float*)d_out;

    cudaFuncSetAttribute(k_conv_mma,
                         cudaFuncAttributeMaxDynamicSharedMemorySize, CONV_SMEM);
    cudaFuncSetAttribute(k2_mma,
                         cudaFuncAttributeMaxDynamicSharedMemorySize, K2_SMEM);

    k_pre<<<2688, 256>>>(x, ec_w1, ec_w2, ga_w1, ga_w2, cd_w1);
    k2_mma<<<B * HW / 64, 128, K2_SMEM>>>(ga_b1, ga_b2);
    k3_cons<<<dim3(4, 4, B * 16), dim3(32, 8)>>>();
    k4_mma<<<256, 256>>>(cd_b1, cd_w2, cd_b2);
    k_conv_mma<<<dim3(8, 16, B), 256, CONV_SMEM>>>(0, 0, ec_b1, x, alpha, out);
    k_conv_mma<<<dim3(8, 16, B), 256, CONV_SMEM>>>(1, 9216, ec_b2, x, alpha, out);
}

// round 8
// speedup vs baseline: 9.0603x; 1.1273x over previous
#include <cuda_runtime.h>
#include <cuda_bf16.h>
#include <math.h>

#define B 2
#define C 64
#define C4 16
#define H 128
#define Wd 128
#define HW (H * Wd)
#define EPSF 1e-6f

typedef unsigned long long u64;
typedef unsigned int u32;

// ---------------- scratch (device globals; no allocation allowed) ----------------
__device__ __align__(16) u32 g_gb[B * C * HW];               // (bf16 gx, bf16 gy) per px
__device__ float g_cons[B * HW];
__device__ float g_ew[B * HW];
__device__ __align__(16) __nv_bfloat16 g_ga2b[B * HW * C4];  // ga2, px-major bf16
__device__ __align__(16) __nv_bfloat16 g_xb[B * HW * C];     // x, NHWC bf16
__device__ __align__(16) __nv_bfloat16 g_eeb[B * HW * C];    // relu(conv1), NHWC bf16
__device__ __align__(16) u64 g_wq[2 * 9 * 4 * 64 * 4];       // conv B fragments
__device__ __align__(16) u64 g_wga1[2048];                   // ga layer1 B fragments
__device__ __align__(16) u64 g_wga2[256];                    // ga layer2 B fragments
__device__ __align__(16) u64 g_wcd[576];                     // cd conv B fragments

__device__ __forceinline__ u32 s2u(const void* p) {
    return (u32)__cvta_generic_to_shared(p);
}

// ---------------- fast math ----------------
__device__ __forceinline__ float fsqrt_ap(float v) {
    float r; asm("sqrt.approx.f32 %0, %1;" : "=f"(r) : "f"(v)); return r;
}
__device__ __forceinline__ float ftanh_ap(float v) {
    float r; asm("tanh.approx.f32 %0, %1;" : "=f"(r) : "f"(v)); return r;
}
__device__ __forceinline__ float frcp_ap(float v) {
    float r; asm("rcp.approx.f32 %0, %1;" : "=f"(r) : "f"(v)); return r;
}
__device__ __forceinline__ float fatan2_ap(float y, float x) {
    float ax = fabsf(x), ay = fabsf(y);
    float mx = fmaxf(ax, ay), mn = fminf(ax, ay);
    float z = __fdividef(mn, fmaxf(mx, 1e-30f));
    float s = z * z;
    float p = fmaf(s, -0.0117212f, 0.0526533f);
    p = fmaf(s, p, -0.1164329f);
    p = fmaf(s, p, 0.1935435f);
    p = fmaf(s, p, -0.3326235f);
    p = fmaf(s, p, 0.9999773f);
    float r = p * z;
    if (ay > ax) r = 1.57079632679f - r;
    if (x < 0.f) r = 3.14159265359f - r;
    return copysignf(r, y);
}

// ---------------- K_PRE: weight packs + g_cons zero + x->NHWC bf16 + sobel ----
// grid.x: [0,128) wprep, [128,640) xprep, [640,2688) sobel 32x32 tiles
__global__ __launch_bounds__(256) void k_pre(const float* __restrict__ x,
                                             const float* __restrict__ w1,
                                             const float* __restrict__ w2,
                                             const float* __restrict__ gw1,
                                             const float* __restrict__ gw2,
                                             const float* __restrict__ cw1) {
    __shared__ __align__(16) char sm[16640];
    int bx = blockIdx.x, tid = threadIdx.x;

    if (bx < 128) {
        int i = bx * 256 + tid;
        g_cons[i] = 0.f;
        if (i < 2 * 9216) {      // ec conv weights
            int cv = i / 9216;
            int r = i % 9216;
            int dlt = r / 1024;
            int r2 = r % 1024;
            int kc = r2 / 256;
            int r3 = r2 % 256;
            int n = r3 / 4, q = r3 % 4;
            const float* w = cv ? w2 : w1;
            int ic0 = kc * 16 + 2 * q;
            __nv_bfloat162 lo = __floats2bfloat162_rn(
                w[(n * 64 + ic0) * 9 + dlt], w[(n * 64 + ic0 + 1) * 9 + dlt]);
            __nv_bfloat162 hi = __floats2bfloat162_rn(
                w[(n * 64 + ic0 + 8) * 9 + dlt], w[(n * 64 + ic0 + 9) * 9 + dlt]);
            g_wq[i] = (u64)(*(u32*)&lo) | ((u64)(*(u32*)&hi) << 32);
        }
        if (i < 2048) {          // ga_w1 fragments, interleaved k: 2c=gx_c, 2c+1=gy_c
            int kstep = i >> 8;
            int nt = (i >> 5) & 7;
            int l = i & 31;
            int n_oc = nt * 8 + (l >> 2);
            int kn0 = kstep * 16 + (l & 3) * 2;   // even
            int ch = kn0 >> 1;
            __nv_bfloat162 lo = __floats2bfloat162_rn(
                gw1[n_oc * 128 + ch], gw1[n_oc * 128 + 64 + ch]);
            __nv_bfloat162 hi = __floats2bfloat162_rn(
                gw1[n_oc * 128 + ch + 4], gw1[n_oc * 128 + 64 + ch + 4]);
            g_wga1[i] = (u64)(*(u32*)&lo) | ((u64)(*(u32*)&hi) << 32);
        }
        if (i < 256) {           // ga_w2 fragments
            int kstep = i >> 6;
            int nt = (i >> 5) & 1;
            int l = i & 31;
            int n_oc = nt * 8 + (l >> 2);
            int k0 = kstep * 16 + (l & 3) * 2;
            __nv_bfloat162 lo = __floats2bfloat162_rn(
                gw2[n_oc * 64 + k0], gw2[n_oc * 64 + k0 + 1]);
            __nv_bfloat162 hi = __floats2bfloat162_rn(
                gw2[n_oc * 64 + k0 + 8], gw2[n_oc * 64 + k0 + 9]);
            g_wga2[i] = (u64)(*(u32*)&lo) | ((u64)(*(u32*)&hi) << 32);
        }
        if (i < 576) {           // cd conv fragments
            int tap = i >> 6;
            int nt = (i >> 5) & 1;
            int l = i & 31;
            int n_oc = nt * 8 + (l >> 2);
            int ic0 = (l & 3) * 2;
            __nv_bfloat162 lo = __floats2bfloat162_rn(
                cw1[(n_oc * 16 + ic0) * 9 + tap],
                cw1[(n_oc * 16 + ic0 + 1) * 9 + tap]);
            __nv_bfloat162 hi = __floats2bfloat162_rn(
                cw1[(n_oc * 16 + ic0 + 8) * 9 + tap],
                cw1[(n_oc * 16 + ic0 + 9) * 9 + tap]);
            g_wcd[i] = (u64)(*(u32*)&lo) | ((u64)(*(u32*)&hi) << 32);
        }
    } else if (bx < 640) {
        // x (NCHW fp32) -> g_xb (NHWC bf16), 64 px per block
        int bb = bx - 128;
        int b = bb >> 8;
        int px0 = (bb & 255) * 64;
        float* s = (float*)sm;
        const float* xb = x + (size_t)b * C * HW;
        for (int i = tid; i < 4096; i += 256) {
            int ic = i >> 6, p = i & 63;
            s[p * 65 + ic] = xb[(size_t)ic * HW + px0 + p];
        }
        __syncthreads();
#pragma unroll
        for (int it = 0; it < 2; it++) {
            int idx = tid + it * 256;
            int p = idx >> 3, seg = idx & 7;
            const float* sp = &s[p * 65 + seg * 8];
            u32 u[4];
#pragma unroll
            for (int k = 0; k < 4; k++) {
                __nv_bfloat162 h2 = __floats2bfloat162_rn(sp[2 * k], sp[2 * k + 1]);
                u[k] = *(u32*)&h2;
            }
            *(uint4*)&g_xb[((size_t)b * HW + px0 + p) * 64 + seg * 8] =
                make_uint4(u[0], u[1], u[2], u[3]);
        }
    } else {
        // depthwise sobel, 32x32 tile -> packed bf16 (gx, gy)
        int z = bx - 640;
        int plane = z >> 4;
        int oy = ((z >> 2) & 3) * 32, ox = (z & 3) * 32;
        float* sx = (float*)sm;
        const float* xp = x + (size_t)plane * HW;
        for (int i = tid; i < 1156; i += 256) {
            int r = i / 34, c = i - r * 34;
            int gh = oy + r - 1, gw = ox + c - 1;
            float v = 0.f;
            if ((unsigned)gh < (unsigned)H && (unsigned)gw < (unsigned)Wd)
                v = xp[gh * Wd + gw];
            sx[r * 34 + c] = v;
        }
        __syncthreads();
#pragma unroll
        for (int k = 0; k < 4; k++) {
            int px = tid + k * 256;
            int row = px >> 5, col = px & 31;
            const float* s0 = sx + row * 34 + col;
            float a00 = s0[0],  a01 = s0[1],  a02 = s0[2];
            float a10 = s0[34],               a12 = s0[36];
            float a20 = s0[68], a21 = s0[69], a22 = s0[70];
            float gx = (a02 - a00) + 2.f * (a12 - a10) + (a22 - a20);
            float gy = (a20 - a00) + 2.f * (a21 - a01) + (a22 - a02);
            __nv_bfloat162 hv = __floats2bfloat162_rn(gx, gy);
            g_gb[plane * HW + (oy + row) * Wd + ox + col] = *(u32*)&hv;
        }
    }
}

// ---------------- K23: merged k3 (consistency) + k2 (1x1 mma chain) -----------
// 128 threads. bi < 2048: k3 one (b,c) channel / 32x32 tile. else: k2, 64 px.
#define K23_SMEM 43328
extern "C" __global__ void __launch_bounds__(128)
k23(const float* __restrict__ b1, const float* __restrict__ b2) {
    extern __shared__ char dsm[];
    int tid = threadIdx.x;
    int bi = blockIdx.x;

    if (bi < 2048) {
        // ---- k3: windowed weighted direction stats, one channel ----
        int b = bi >> 10;
        int rem = bi & 1023;
        int c = rem >> 4;
        int tile = rem & 15;
        int oy = (tile >> 2) * 32, ox = (tile & 3) * 32;
        float* sm0 = (float*)dsm;
        float* sm1 = sm0 + 1296;
        float* sm2 = sm1 + 1296;
        float* h0 = sm2 + 1296;
        float* h1 = h0 + 1152;
        float* h2 = h1 + 1152;

        const u32* gb = g_gb + (size_t)(b * C + c) * HW;
        for (int i = tid; i < 1296; i += 128) {
            int r = i / 36, k = i - r * 36;
            int gh = oy + r - 2, gw = ox + k - 2;
            float m0 = 0.f, m1 = 0.f, m2 = 0.f;
            if ((unsigned)gh < (unsigned)H && (unsigned)gw < (unsigned)Wd) {
                u32 v = gb[gh * Wd + gw];
                float2 g = __bfloat1622float2(*(__nv_bfloat162*)&v);
                float gx = g.x, gy = g.y;
                float mag = fsqrt_ap(gx * gx + gy * gy + EPSF);
                float dir = fatan2_ap(gy, gx);
                m0 = mag;
                m1 = mag * dir;
                m2 = m1 * dir;
            }
            sm0[i] = m0;
            sm1[i] = m1;
            sm2[i] = m2;
        }
        __syncthreads();
        for (int i = tid; i < 1152; i += 128) {
            int r = i >> 5, k = i & 31;
            const float* p0 = sm0 + r * 36 + k;
            const float* p1 = sm1 + r * 36 + k;
            const float* p2 = sm2 + r * 36 + k;
            float a0 = 0.f, a1 = 0.f, a2 = 0.f;
#pragma unroll
            for (int d = 0; d < 5; d++) {
                a0 += p0[d];
                a1 += p1[d];
                a2 += p2[d];
            }
            h0[i] = a0;
            h1[i] = a1;
            h2[i] = a2;
        }
        __syncthreads();
        int ty = tid >> 5, tx = tid & 31;
#pragma unroll
        for (int j = 0; j < 8; j++) {
            int row = j * 4 + ty;
            float s0 = 0.f, s1 = 0.f, s2 = 0.f;
#pragma unroll
            for (int d = 0; d < 5; d++) {
                s0 += h0[(row + d) * 32 + tx];
                s1 += h1[(row + d) * 32 + tx];
                s2 += h2[(row + d) * 32 + tx];
            }
            float inv = frcp_ap(s0 + EPSF);
            float wmean = s1 * inv;
            float wvar = (s2 - 2.f * wmean * s1 + wmean * wmean * s0) * inv;
            wvar = fmaxf(wvar, 0.f);
            float cv = (1.f - ftanh_ap(fsqrt_ap(wvar))) * (1.f / (float)C);
            atomicAdd(&g_cons[b * HW + (oy + row) * Wd + (ox + tx)], cv);
        }
        return;
    }

    // ---- k2: fused 1x1 chain via bf16 mma (128 -> 64 relu -> 16 relu) ----
    __nv_bfloat16* sIn = (__nv_bfloat16*)dsm;
    __nv_bfloat16* sHid = (__nv_bfloat16*)(dsm + 16384);
    u64* sW1 = (u64*)(dsm + 24576);
    u64* sW2 = (u64*)(dsm + 40960);
    float* sb1 = (float*)(dsm + 43008);
    float* sb2 = (float*)(dsm + 43264);

    int lane = tid & 31, w = tid >> 5;
    int bk = bi - 2048;
    int b = bk >> 8;
    int px0 = (bk & 255) * 64;

    {
        const float4* s1 = (const float4*)g_wga1;
        float4* d1 = (float4*)sW1;
#pragma unroll
        for (int i = tid; i < 1024; i += 128) d1[i] = s1[i];
        ((float4*)sW2)[tid] = ((const float4*)g_wga2)[tid];
        if (tid < 64) sb1[tid] = b1[tid];
        if (tid < 16) sb2[tid] = b2[tid];
    }
    // stage input: packed (gx,gy) bf16 pairs -> px-major swizzled, k interleaved
    const u32* gbb = g_gb + (size_t)b * C * HW + px0;
    for (int i = tid; i < 4096; i += 128) {
        int cp = i >> 6, px = i & 63;
        u32 v = gbb[(size_t)cp * HW + px];
        int half = cp >> 5, c4 = (cp & 31) * 4;
        *(u32*)(dsm + half * 8192 + px * 128 +
                ((u32)c4 ^ ((u32)(px & 7) << 4))) = v;
    }
    __syncthreads();

    int m = lane & 15, kb = (lane >> 4) << 4;
    int p = w * 16 + m;
    u32 swz = (u32)((p & 7) << 4);
    u32 arow = s2u(sIn) + p * 128;

    float acc[8][4];
#pragma unroll
    for (int nt = 0; nt < 8; nt++)
#pragma unroll
        for (int k = 0; k < 4; k++) acc[nt][k] = 0.f;

#pragma unroll
    for (int kc = 0; kc < 8; kc++) {
        u32 a0, a1, a2, a3;
        u32 addr = arow + (kc >> 2) * 8192 + (((u32)((kc & 3) * 32 + kb)) ^ swz);
        asm volatile(
            "ldmatrix.sync.aligned.m8n8.x4.shared.b16 {%0,%1,%2,%3}, [%4];"
            : "=r"(a0), "=r"(a1), "=r"(a2), "=r"(a3) : "r"(addr));
        const u64* wk = sW1 + (size_t)kc * 256 + lane;
#pragma unroll
        for (int nt = 0; nt < 8; nt++) {
            u64 bv = wk[nt * 32];
            u32 bf0 = (u32)bv, bf1 = (u32)(bv >> 32);
            asm volatile(
                "mma.sync.aligned.m16n8k16.row.col.f32.bf16.bf16.f32 "
                "{%0,%1,%2,%3}, {%4,%5,%6,%7}, {%8,%9}, {%0,%1,%2,%3};"
                : "+f"(acc[nt][0]), "+f"(acc[nt][1]),
                  "+f"(acc[nt][2]), "+f"(acc[nt][3])
                : "r"(a0), "r"(a1), "r"(a2), "r"(a3), "r"(bf0), "r"(bf1));
        }
    }

    int rr = lane >> 2, cc0 = (lane & 3) * 2;
    int pr0 = w * 16 + rr, pr1 = pr0 + 8;
#pragma unroll
    for (int nt = 0; nt < 8; nt++) {
        int oc = nt * 8 + cc0;
        float bb0 = sb1[oc], bb1 = sb1[oc + 1];
        __nv_bfloat162 v01 = __floats2bfloat162_rn(
            fmaxf(acc[nt][0] + bb0, 0.f), fmaxf(acc[nt][1] + bb1, 0.f));
        __nv_bfloat162 v23 = __floats2bfloat162_rn(
            fmaxf(acc[nt][2] + bb0, 0.f), fmaxf(acc[nt][3] + bb1, 0.f));
        *(u32*)((char*)sHid + pr0 * 128 +
                ((u32)(oc * 2) ^ ((u32)(pr0 & 7) << 4))) = *(u32*)&v01;
        *(u32*)((char*)sHid + pr1 * 128 +
                ((u32)(oc * 2) ^ ((u32)(pr1 & 7) << 4))) = *(u32*)&v23;
    }
    __syncwarp();

    float a2c[2][4];
#pragma unroll
    for (int nt = 0; nt < 2; nt++)
#pragma unroll
        for (int k = 0; k < 4; k++) a2c[nt][k] = 0.f;

    u32 hrow = s2u(sHid) + p * 128;
#pragma unroll
    for (int kc = 0; kc < 4; kc++) {
        u32 a0, a1, a2, a3;
        u32 addr = hrow + (((u32)(kc * 32 + kb)) ^ swz);
        asm volatile(
            "ldmatrix.sync.aligned.m8n8.x4.shared.b16 {%0,%1,%2,%3}, [%4];"
            : "=r"(a0), "=r"(a1), "=r"(a2), "=r"(a3) : "r"(addr));
        const u64* wk = sW2 + (size_t)kc * 64 + lane;
#pragma unroll
        for (int nt = 0; nt < 2; nt++) {
            u64 bv = wk[nt * 32];
            u32 bf0 = (u32)bv, bf1 = (u32)(bv >> 32);
            asm volatile(
                "mma.sync.aligned.m16n8k16.row.col.f32.bf16.bf16.f32 "
                "{%0,%1,%2,%3}, {%4,%5,%6,%7}, {%8,%9}, {%0,%1,%2,%3};"
                : "+f"(a2c[nt][0]), "+f"(a2c[nt][1]),
                  "+f"(a2c[nt][2]), "+f"(a2c[nt][3])
                : "r"(a0), "r"(a1), "r"(a2), "r"(a3), "r"(bf0), "r"(bf1));
        }
    }

    size_t pxg0 = (size_t)b * HW + px0 + w * 16 + rr;
#pragma unroll
    for (int nt = 0; nt < 2; nt++) {
        int oc = nt * 8 + cc0;
        float bb0 = sb2[oc], bb1 = sb2[oc + 1];
        __nv_bfloat162 v01 = __floats2bfloat162_rn(
            fmaxf(a2c[nt][0] + bb0, 0.f), fmaxf(a2c[nt][1] + bb1, 0.f));
        __nv_bfloat162 v23 = __floats2bfloat162_rn(
            fmaxf(a2c[nt][2] + bb0, 0.f), fmaxf(a2c[nt][3] + bb1, 0.f));
        *(u32*)&g_ga2b[pxg0 * 16 + oc] = *(u32*)&v01;
        *(u32*)&g_ga2b[(pxg0 + 8) * 16 + oc] = *(u32*)&v23;
    }
}

// ---------------- KMID: merged conv1 (mode 0) + k4 (cd branch) ----------------
#define XS_BYTES 23040
#define WS_BYTES 73728
#define CONV_SMEM (XS_BYTES + WS_BYTES)

extern "C" __global__ void __launch_bounds__(256)
kmid(const float* __restrict__ ecb1,
     const float* __restrict__ cb1, const float* __restrict__ cw2,
     const float* __restrict__ cb2) {
    extern __shared__ char dsm[];
    __shared__ float sbias[64];
    int tid = threadIdx.x;
    int lane = tid & 31, w = tid >> 5;
    int bi = blockIdx.x;

    if (bi < 256) {
        // ---- conv1: 3x3 64->64 bf16 mma, relu -> g_eeb ----
        __nv_bfloat16* Xs = (__nv_bfloat16*)dsm;
        u64* Ws = (u64*)(dsm + XS_BYTES);
        int b = bi >> 7;
        int rem = bi & 127;
        int brow = (rem >> 3) * 8, bcol = (rem & 7) * 16;

        {
            const float4* src = (const float4*)g_wq;
            float4* dst = (float4*)Ws;
            for (int i = tid; i < WS_BYTES / 16; i += 256) dst[i] = src[i];
        }
        if (tid < 64) sbias[tid] = ecb1[tid];

        const __nv_bfloat16* xb = g_xb + (size_t)b * HW * 64;
        for (int i = tid; i < 180 * 8; i += 256) {
            int p = i >> 3, seg = i & 7;
            int r = p / 18, c = p - r * 18;
            int gh = brow - 1 + r, gc = bcol - 1 + c;
            uint4 v = make_uint4(0, 0, 0, 0);
            if ((unsigned)gh < (unsigned)H && (unsigned)gc < (unsigned)Wd)
                v = *(const uint4*)((const char*)xb +
                                    ((size_t)(gh * Wd + gc)) * 128 + seg * 16);
            *(uint4*)((char*)Xs + p * 128 + ((seg * 16) ^ ((p & 7) << 4))) = v;
        }
        __syncthreads();

        float acc[8][4];
#pragma unroll
        for (int nt = 0; nt < 8; nt++)
#pragma unroll
            for (int k = 0; k < 4; k++) acc[nt][k] = 0.f;

        u32 xs_base = s2u(Xs);
        int m = lane & 15;
        int kb = (lane >> 4) << 4;
        int nq = (lane >> 2) * 4 + (lane & 3);

#pragma unroll
        for (int ky = 0; ky < 3; ky++) {
#pragma unroll
            for (int kx = 0; kx < 3; kx++) {
                int p = (w + ky) * 18 + kx + m;
                u32 arow = xs_base + p * 128;
                u32 swz = (u32)((p & 7) << 4);
                const u64* wd = Ws + ((ky * 3 + kx) * 4) * 256 + nq;
#pragma unroll
                for (int kc = 0; kc < 4; kc++) {
                    u32 a0, a1, a2, a3;
                    u32 addr = arow + ((u32)(kc * 32 + kb) ^ swz);
                    asm volatile(
                        "ldmatrix.sync.aligned.m8n8.x4.shared.b16 "
                        "{%0,%1,%2,%3}, [%4];"
                        : "=r"(a0), "=r"(a1), "=r"(a2), "=r"(a3)
                        : "r"(addr));
                    const u64* wk = wd + kc * 256;
#pragma unroll
                    for (int nt = 0; nt < 8; nt++) {
                        u64 bv = wk[nt * 32];
                        u32 b0 = (u32)bv, b1 = (u32)(bv >> 32);
                        asm volatile(
                            "mma.sync.aligned.m16n8k16.row.col.f32.bf16.bf16.f32 "
                            "{%0,%1,%2,%3}, {%4,%5,%6,%7}, {%8,%9}, {%0,%1,%2,%3};"
                            : "+f"(acc[nt][0]), "+f"(acc[nt][1]),
                              "+f"(acc[nt][2]), "+f"(acc[nt][3])
                            : "r"(a0), "r"(a1), "r"(a2), "r"(a3),
                              "r"(b0), "r"(b1));
                    }
                }
            }
        }

        int g = lane >> 2, t = lane & 3;
        int h = brow + w;
        size_t px0 = (size_t)b * HW + h * Wd + bcol + g;
#pragma unroll
        for (int nt = 0; nt < 8; nt++) {
            int oc = nt * 8 + 2 * t;
            float b0f = sbias[oc], b1f = sbias[oc + 1];
            __nv_bfloat162 p01 = __floats2bfloat162_rn(
                fmaxf(acc[nt][0] + b0f, 0.f), fmaxf(acc[nt][1] + b1f, 0.f));
            __nv_bfloat162 p23 = __floats2bfloat162_rn(
                fmaxf(acc[nt][2] + b0f, 0.f), fmaxf(acc[nt][3] + b1f, 0.f));
            *(u32*)&g_eeb[px0 * 64 + oc] = *(u32*)&p01;
            *(u32*)&g_eeb[(px0 + 8) * 64 + oc] = *(u32*)&p23;
        }
        return;
    }

    // ---- k4: cd branch (3x3 16->16 relu, 1x1->1, sigmoid * cons) ----
    char* sga = dsm;                       // 180*48 = 8640
    u64* sW = (u64*)(dsm + 8640);          // 576 u64
    __shared__ float b1s[16], w2s[16];
    __shared__ float b2s_;

    int bk = bi - 256;
    int b = bk >> 7;
    int t8 = bk & 127;
    int brow = (t8 >> 3) * 8, bcol = (t8 & 7) * 16;

    for (int i = tid; i < 576; i += 256) sW[i] = g_wcd[i];
    if (tid < 16) { b1s[tid] = cb1[tid]; w2s[tid] = cw2[tid]; }
    if (tid == 0) b2s_ = cb2[0];

    const __nv_bfloat16* gb = g_ga2b + (size_t)b * HW * 16;
    for (int i = tid; i < 360; i += 256) {
        int p = i >> 1, hf = i & 1;
        int r = p / 18, c = p - r * 18;
        int gh = brow - 1 + r, gc = bcol - 1 + c;
        uint4 v = make_uint4(0, 0, 0, 0);
        if ((unsigned)gh < (unsigned)H && (unsigned)gc < (unsigned)Wd)
            v = *(const uint4*)&gb[(size_t)(gh * Wd + gc) * 16 + hf * 8];
        *(uint4*)(sga + p * 48 + hf * 16) = v;
    }
    __syncthreads();

    float acc[2][4];
#pragma unroll
    for (int nt = 0; nt < 2; nt++)
#pragma unroll
        for (int k = 0; k < 4; k++) acc[nt][k] = 0.f;

    int m = lane & 15, kb = (lane >> 4) << 4;
    u32 base = s2u(sga);
#pragma unroll
    for (int ky = 0; ky < 3; ky++) {
#pragma unroll
        for (int kx = 0; kx < 3; kx++) {
            int tap = ky * 3 + kx;
            u32 addr = base + (u32)(((w + ky) * 18 + kx + m) * 48 + kb);
            u32 a0, a1, a2, a3;
            asm volatile(
                "ldmatrix.sync.aligned.m8n8.x4.shared.b16 {%0,%1,%2,%3}, [%4];"
                : "=r"(a0), "=r"(a1), "=r"(a2), "=r"(a3) : "r"(addr));
            const u64* wk = sW + tap * 64 + lane;
#pragma unroll
            for (int nt = 0; nt < 2; nt++) {
                u64 bv = wk[nt * 32];
                u32 bf0 = (u32)bv, bf1 = (u32)(bv >> 32);
                asm volatile(
                    "mma.sync.aligned.m16n8k16.row.col.f32.bf16.bf16.f32 "
                    "{%0,%1,%2,%3}, {%4,%5,%6,%7}, {%8,%9}, {%0,%1,%2,%3};"
                    : "+f"(acc[nt][0]), "+f"(acc[nt][1]),
                      "+f"(acc[nt][2]), "+f"(acc[nt][3])
                    : "r"(a0), "r"(a1), "r"(a2), "r"(a3), "r"(bf0), "r"(bf1));
            }
        }
    }

    int r0 = lane >> 2, t = lane & 3;
    float p0 = 0.f, p1 = 0.f;
#pragma unroll
    for (int nt = 0; nt < 2; nt++) {
        int oc = nt * 8 + 2 * t;
        float w0 = w2s[oc], w1v = w2s[oc + 1];
        float bb0 = b1s[oc], bb1 = b1s[oc + 1];
        p0 += w0 * fmaxf(acc[nt][0] + bb0, 0.f) + w1v * fmaxf(acc[nt][1] + bb1, 0.f);
        p1 += w0 * fmaxf(acc[nt][2] + bb0, 0.f) + w1v * fmaxf(acc[nt][3] + bb1, 0.f);
    }
    p0 += __shfl_xor_sync(0xffffffffu, p0, 1);
    p0 += __shfl_xor_sync(0xffffffffu, p0, 2);
    p1 += __shfl_xor_sync(0xffffffffu, p1, 1);
    p1 += __shfl_xor_sync(0xffffffffu, p1, 2);

    if (t == 0) {
        int gpx = (brow + w) * Wd + bcol + r0;
        float s0 = p0 + b2s_, s1 = p1 + b2s_;
        g_ew[b * HW + gpx] =
            frcp_ap(1.f + __expf(-s0)) * g_cons[b * HW + gpx];
        g_ew[b * HW + gpx + 8] =
            frcp_ap(1.f + __expf(-s1)) * g_cons[b * HW + gpx + 8];
    }
}

// ---------------- conv2: 3x3 conv 64->64 + residual epilogue -------------------
extern "C" __global__ void __launch_bounds__(256, 2)
k_conv2(const float* __restrict__ bias,
        const float* __restrict__ xres, const float* __restrict__ alphap,
        float* __restrict__ out) {
    extern __shared__ char dsm[];
    __nv_bfloat16* Xs = (__nv_bfloat16*)dsm;
    u64* Ws = (u64*)(dsm + XS_BYTES);
    __shared__ float sbias[64];

    int tid = threadIdx.x;
    int lane = tid & 31, w = tid >> 5;
    int bcol = blockIdx.x * 16, brow = blockIdx.y * 8;
    int b = blockIdx.z;

    {
        const float4* src = (const float4*)(g_wq + 9216);
        float4* dst = (float4*)Ws;
        for (int i = tid; i < WS_BYTES / 16; i += 256) dst[i] = src[i];
    }
    if (tid < 64) sbias[tid] = bias[tid];

    const __nv_bfloat16* xb = g_eeb + (size_t)b * HW * 64;
    for (int i = tid; i < 180 * 8; i += 256) {
        int p = i >> 3, seg = i & 7;
        int r = p / 18, c = p - r * 18;
        int gh = brow - 1 + r, gc = bcol - 1 + c;
        uint4 v = make_uint4(0, 0, 0, 0);
        if ((unsigned)gh < (unsigned)H && (unsigned)gc < (unsigned)Wd)
            v = *(const uint4*)((const char*)xb +
                                ((size_t)(gh * Wd + gc)) * 128 + seg * 16);
        *(uint4*)((char*)Xs + p * 128 + ((seg * 16) ^ ((p & 7) << 4))) = v;
    }
    __syncthreads();

    float acc[8][4];
#pragma unroll
    for (int nt = 0; nt < 8; nt++)
#pragma unroll
        for (int k = 0; k < 4; k++) acc[nt][k] = 0.f;

    u32 xs_base = s2u(Xs);
    int m = lane & 15;
    int kb = (lane >> 4) << 4;
    int nq = (lane >> 2) * 4 + (lane & 3);

#pragma unroll
    for (int ky = 0; ky < 3; ky++) {
#pragma unroll
        for (int kx = 0; kx < 3; kx++) {
            int p = (w + ky) * 18 + kx + m;
            u32 arow = xs_base + p * 128;
            u32 swz = (u32)((p & 7) << 4);
            const u64* wd = Ws + ((ky * 3 + kx) * 4) * 256 + nq;
#pragma unroll
            for (int kc = 0; kc < 4; kc++) {
                u32 a0, a1, a2, a3;
                u32 addr = arow + ((u32)(kc * 32 + kb) ^ swz);
                asm volatile(
                    "ldmatrix.sync.aligned.m8n8.x4.shared.b16 "
                    "{%0,%1,%2,%3}, [%4];"
                    : "=r"(a0), "=r"(a1), "=r"(a2), "=r"(a3)
                    : "r"(addr));
                const u64* wk = wd + kc * 256;
#pragma unroll
                for (int nt = 0; nt < 8; nt++) {
                    u64 bv = wk[nt * 32];
                    u32 b0 = (u32)bv, b1 = (u32)(bv >> 32);
                    asm volatile(
                        "mma.sync.aligned.m16n8k16.row.col.f32.bf16.bf16.f32 "
                        "{%0,%1,%2,%3}, {%4,%5,%6,%7}, {%8,%9}, {%0,%1,%2,%3};"
                        : "+f"(acc[nt][0]), "+f"(acc[nt][1]),
                          "+f"(acc[nt][2]), "+f"(acc[nt][3])
                        : "r"(a0), "r"(a1), "r"(a2), "r"(a3),
                          "r"(b0), "r"(b1));
                }
            }
        }
    }

    int g = lane >> 2, t = lane & 3;
    float* sep = (float*)dsm;
    __syncthreads();
    int pl0 = w * 16 + g;
#pragma unroll
    for (int nt = 0; nt < 8; nt++) {
        int oc = nt * 8 + 2 * t;
        sep[oc * 132 + pl0]           = acc[nt][0] + sbias[oc];
        sep[(oc + 1) * 132 + pl0]     = acc[nt][1] + sbias[oc + 1];
        sep[oc * 132 + pl0 + 8]       = acc[nt][2] + sbias[oc];
        sep[(oc + 1) * 132 + pl0 + 8] = acc[nt][3] + sbias[oc + 1];
    }
    __syncthreads();
    float alpha = __ldg(alphap);
    for (int i = tid; i < 8192; i += 256) {
        int oc = i >> 7, pxl = i & 127;
        int h = brow + (pxl >> 4), col = bcol + (pxl & 15);
        int gpx = h * Wd + col;
        float v = sep[oc * 132 + pxl];
        float e = g_ew[b * HW + gpx];
        size_t oi = ((size_t)b * C + oc) * HW + gpx;
        out[oi] = xres[oi] + alpha * e * v;
    }
}

// ---------------- launch ----------------
extern "C" void kernel_launch(void* const* d_in, const int* in_sizes, int n_in,
                              void* d_out, int out_size) {
    const float* x     = (const float*)d_in[0];
    const float* ga_w1 = (const float*)d_in[3];
    const float* ga_b1 = (const float*)d_in[4];
    const float* ga_w2 = (const float*)d_in[5];
    const float* ga_b2 = (const float*)d_in[6];
    const float* cd_w1 = (const float*)d_in[7];
    const float* cd_b1 = (const float*)d_in[8];
    const float* cd_w2 = (const float*)d_in[9];
    const float* cd_b2 = (const float*)d_in[10];
    const float* ec_w1 = (const float*)d_in[11];
    const float* ec_b1 = (const float*)d_in[12];
    const float* ec_w2 = (const float*)d_in[13];
    const float* ec_b2 = (const float*)d_in[14];
    const float* alpha = (const float*)d_in[15];
    float* out = (float*)d_out;

    cudaFuncSetAttribute(k23,
                         cudaFuncAttributeMaxDynamicSharedMemorySize, K23_SMEM);
    cudaFuncSetAttribute(kmid,
                         cudaFuncAttributeMaxDynamicSharedMemorySize, CONV_SMEM);
    cudaFuncSetAttribute(k_conv2,
                         cudaFuncAttributeMaxDynamicSharedMemorySize, CONV_SMEM);

    k_pre<<<2688, 256>>>(x, ec_w1, ec_w2, ga_w1, ga_w2, cd_w1);
    k23<<<2048 + B * HW / 64, 128, K23_SMEM>>>(ga_b1, ga_b2);
    kmid<<<512, 256, CONV_SMEM>>>(ec_b1, cd_b1, cd_w2, cd_b2);
    k_conv2<<<dim3(8, 16, B), 256, CONV_SMEM>>>(ec_b2, x, alpha, out);
}